// round 1
// baseline (speedup 1.0000x reference)
#include <cuda_runtime.h>
#include <cuda_bf16.h>
#include <math.h>

// Problem constants
#define NB 2048     // queries
#define NS 16384    // supports
#define ND 512      // dim
#define NC 17       // classes
#define KTOP 8
#define TAU 10.0f
#define EPS 1e-12f

// ---------------- scratch (device globals; no runtime alloc) ----------------
__device__ float g_zn[NB * ND];            // normalized z
__device__ float g_sn[NS * ND];            // normalized supports
__device__ float g_cent[NC * ND];          // centroids
__device__ float g_centn[NC * ND];         // normalized centroids
__device__ float g_cnt[NC];                // label column sums
__device__ int   g_labcls[NS];             // argmax(labels) per support
__device__ int   g_predcls[NS];            // argmax(temp_labels) per support
__device__ float g_soft[NS * NC];          // softmax(temp_labels)
__device__ float g_part[64 * NC * ND];     // centroid partials (64 n-chunks)
__device__ float g_cos[(size_t)NB * NS];   // query-support cosine (134 MB)

// ---------------- f32x2 helpers ----------------
__device__ __forceinline__ unsigned long long dup_f32(float x) {
    unsigned long long r;
    unsigned u = __float_as_uint(x);
    asm("mov.b64 %0, {%1, %1};" : "=l"(r) : "r"(u));
    return r;
}
__device__ __forceinline__ void ffma2(unsigned long long &c, unsigned long long a,
                                      unsigned long long b) {
    asm("fma.rn.f32x2 %0, %1, %2, %0;" : "+l"(c) : "l"(a), "l"(b));
}

// ---------------- row normalization: z and supports ----------------
__global__ void k_normalize(const float* __restrict__ z, const float* __restrict__ sup) {
    int gw = (blockIdx.x * blockDim.x + threadIdx.x) >> 5;
    int lane = threadIdx.x & 31;
    if (gw >= NB + NS) return;
    const float* src;
    float* dst;
    if (gw < NB) { src = z   + (size_t)gw * ND;        dst = g_zn + (size_t)gw * ND; }
    else         { src = sup + (size_t)(gw - NB) * ND; dst = g_sn + (size_t)(gw - NB) * ND; }
    float v[16];
    float ss = 0.f;
#pragma unroll
    for (int i = 0; i < 16; i++) {
        float x = src[lane + 32 * i];
        v[i] = x;
        ss += x * x;
    }
#pragma unroll
    for (int o = 16; o; o >>= 1) ss += __shfl_xor_sync(0xffffffffu, ss, o);
    float inv = 1.f / fmaxf(sqrtf(ss), EPS);
#pragma unroll
    for (int i = 0; i < 16; i++) dst[lane + 32 * i] = v[i] * inv;
}

// ---------------- label argmax per support ----------------
__global__ void k_labcls(const float* __restrict__ labels) {
    int n = blockIdx.x * blockDim.x + threadIdx.x;
    if (n >= NS) return;
    const float* r = labels + n * NC;
    float m = r[0]; int mi = 0;
#pragma unroll
    for (int c = 1; c < NC; c++) { float x = r[c]; if (x > m) { m = x; mi = c; } }
    g_labcls[n] = mi;
}

// ---------------- label column sums (deterministic) ----------------
__global__ void k_colsum(const float* __restrict__ labels) {
    __shared__ float sh[256];
    int c = blockIdx.x, tid = threadIdx.x;
    float s = 0.f;
    for (int n = tid; n < NS; n += 256) s += labels[n * NC + c];
    sh[tid] = s;
    __syncthreads();
    for (int st = 128; st; st >>= 1) {
        if (tid < st) sh[tid] += sh[tid + st];
        __syncthreads();
    }
    if (tid == 0) g_cnt[c] = sh[0];
}

// ---------------- centroid partials per n-chunk (atomic-free) ----------------
__global__ void k_cent_part(const float* __restrict__ sup) {
    __shared__ float sp[NC * ND];  // 34816 B
    int tid = threadIdx.x;  // 512 threads, one per dim
    for (int i = tid; i < NC * ND; i += 512) sp[i] = 0.f;
    __syncthreads();
    int n0 = blockIdx.x * 256;
    for (int n = 0; n < 256; n++) {
        int c = g_labcls[n0 + n];
        sp[c * ND + tid] += sup[(size_t)(n0 + n) * ND + tid];
    }
    __syncthreads();
    float* dst = g_part + (size_t)blockIdx.x * NC * ND;
    for (int i = tid; i < NC * ND; i += 512) dst[i] = sp[i];
}

__global__ void k_cent_reduce() {
    int i = blockIdx.x * blockDim.x + threadIdx.x;
    if (i >= NC * ND) return;
    float s = 0.f;
    for (int b = 0; b < 64; b++) s += g_part[(size_t)b * NC * ND + i];
    int c = i / ND;
    g_cent[i] = s / (g_cnt[c] + EPS);
}

__global__ void k_cent_norm() {
    int w = threadIdx.x >> 5, lane = threadIdx.x & 31;
    if (w >= NC) return;
    float v[16];
    float ss = 0.f;
#pragma unroll
    for (int i = 0; i < 16; i++) {
        float x = g_cent[w * ND + lane + 32 * i];
        v[i] = x; ss += x * x;
    }
#pragma unroll
    for (int o = 16; o; o >>= 1) ss += __shfl_xor_sync(0xffffffffu, ss, o);
    float inv = 1.f / fmaxf(sqrtf(ss), EPS);
#pragma unroll
    for (int i = 0; i < 16; i++) g_centn[w * ND + lane + 32 * i] = v[i] * inv;
}

// ---------------- temp_labels: per support argmax class + softmax ----------------
__global__ void k_templabels() {
    __shared__ float sc[NC * ND];
    int tid = threadIdx.x;
    for (int i = tid; i < NC * ND; i += 256) sc[i] = g_centn[i];
    __syncthreads();
    int w = tid >> 5, lane = tid & 31;
    int row = blockIdx.x * 8 + w;
    float acc[NC];
#pragma unroll
    for (int c = 0; c < NC; c++) acc[c] = 0.f;
    const float* sr = g_sn + (size_t)row * ND;
#pragma unroll 4
    for (int i = 0; i < 16; i++) {
        float x = sr[lane + 32 * i];
#pragma unroll
        for (int c = 0; c < NC; c++) acc[c] += x * sc[c * ND + lane + 32 * i];
    }
#pragma unroll
    for (int c = 0; c < NC; c++) {
#pragma unroll
        for (int o = 16; o; o >>= 1) acc[c] += __shfl_xor_sync(0xffffffffu, acc[c], o);
    }
    if (lane == 0) {
        float t[NC];
        float m = -1e30f; int mi = 0;
#pragma unroll
        for (int c = 0; c < NC; c++) {
            t[c] = TAU * acc[c];
            if (t[c] > m) { m = t[c]; mi = c; }
        }
        float s = 0.f;
#pragma unroll
        for (int c = 0; c < NC; c++) { t[c] = expf(t[c] - m); s += t[c]; }
#pragma unroll
        for (int c = 0; c < NC; c++) g_soft[row * NC + c] = t[c] / s;
        g_predcls[row] = mi;
    }
}

// ---------------- main GEMM: cos = zn @ sn^T  (fp32 via FFMA2) ----------------
#define BM 128
#define BN 128
#define BK 16
__global__ __launch_bounds__(256, 2) void k_gemm() {
    __shared__ __align__(16) float As[BK][BM];
    __shared__ __align__(16) float Bs[BK][BN];
    const int tid = threadIdx.x;
    const int tx = tid & 15, ty = tid >> 4;
    const int brow = blockIdx.y * BM;
    const int bcol = blockIdx.x * BN;

    unsigned long long acc[8][4];
#pragma unroll
    for (int i = 0; i < 8; i++)
#pragma unroll
        for (int j = 0; j < 4; j++) acc[i][j] = 0ULL;

    const int lrow = tid >> 2;          // 0..63
    const int lq = (tid & 3) * 4;       // 0,4,8,12
    const float* Ap = g_zn + (size_t)(brow + lrow) * ND + lq;
    const float* Bp = g_sn + (size_t)(bcol + lrow) * ND + lq;

    for (int k0 = 0; k0 < ND; k0 += BK) {
        float4 a0 = *(const float4*)(Ap + k0);
        float4 a1 = *(const float4*)(Ap + (size_t)64 * ND + k0);
        float4 b0 = *(const float4*)(Bp + k0);
        float4 b1 = *(const float4*)(Bp + (size_t)64 * ND + k0);
        __syncthreads();
        As[lq + 0][lrow] = a0.x; As[lq + 1][lrow] = a0.y;
        As[lq + 2][lrow] = a0.z; As[lq + 3][lrow] = a0.w;
        As[lq + 0][lrow + 64] = a1.x; As[lq + 1][lrow + 64] = a1.y;
        As[lq + 2][lrow + 64] = a1.z; As[lq + 3][lrow + 64] = a1.w;
        Bs[lq + 0][lrow] = b0.x; Bs[lq + 1][lrow] = b0.y;
        Bs[lq + 2][lrow] = b0.z; Bs[lq + 3][lrow] = b0.w;
        Bs[lq + 0][lrow + 64] = b1.x; Bs[lq + 1][lrow + 64] = b1.y;
        Bs[lq + 2][lrow + 64] = b1.z; Bs[lq + 3][lrow + 64] = b1.w;
        __syncthreads();
#pragma unroll
        for (int k = 0; k < BK; k++) {
            const float* ap = &As[k][ty * 8];
            float4 af0 = *(const float4*)(ap);
            float4 af1 = *(const float4*)(ap + 4);
            ulonglong2 bp0 = *(const ulonglong2*)(&Bs[k][tx * 8]);
            ulonglong2 bp1 = *(const ulonglong2*)(&Bs[k][tx * 8 + 4]);
            float a_[8] = {af0.x, af0.y, af0.z, af0.w, af1.x, af1.y, af1.z, af1.w};
            unsigned long long bq[4] = {bp0.x, bp0.y, bp1.x, bp1.y};
#pragma unroll
            for (int i = 0; i < 8; i++) {
                unsigned long long da = dup_f32(a_[i]);
#pragma unroll
                for (int j = 0; j < 4; j++) ffma2(acc[i][j], da, bq[j]);
            }
        }
    }

#pragma unroll
    for (int i = 0; i < 8; i++) {
        size_t off = (size_t)(brow + ty * 8 + i) * NS + bcol + tx * 8;
#pragma unroll
        for (int j = 0; j < 4; j++) {
            *(unsigned long long*)(g_cos + off + 2 * j) = acc[i][j];
        }
    }
}

// ---------------- per-row top-8 + targets/outputs ----------------
__global__ void k_topk(float* __restrict__ out) {
    __shared__ float hv[256];
    __shared__ int hid[256];
    __shared__ int widx[KTOP];
    __shared__ float st[NC], so[NC], ssum[2];
    const int row = blockIdx.x;
    const int tid = threadIdx.x;
    const float* W = g_cos + (size_t)row * NS;

    float v[KTOP];
    int id[KTOP];
#pragma unroll
    for (int i = 0; i < KTOP; i++) { v[i] = -1e30f; id[i] = 1 << 30; }

    // each thread scans 64 strided columns, keeps local sorted-desc top-8
    for (int t = 0; t < NS / 256; t++) {
        int j = tid + (t << 8);
        float x = W[j];
        if (x > v[KTOP - 1]) {
            v[KTOP - 1] = x; id[KTOP - 1] = j;
#pragma unroll
            for (int i = KTOP - 1; i >= 1; i--) {
                if (v[i] > v[i - 1]) {
                    float tv = v[i]; v[i] = v[i - 1]; v[i - 1] = tv;
                    int ti = id[i]; id[i] = id[i - 1]; id[i - 1] = ti;
                }
            }
        }
    }

    // 8 tournament rounds; tie -> lower index (matches jax top_k set semantics)
    for (int r = 0; r < KTOP; r++) {
        hv[tid] = v[0];
        hid[tid] = id[0];
        __syncthreads();
        for (int s = 128; s; s >>= 1) {
            if (tid < s) {
                float v2 = hv[tid + s]; int i2 = hid[tid + s];
                if (v2 > hv[tid] || (v2 == hv[tid] && i2 < hid[tid])) {
                    hv[tid] = v2; hid[tid] = i2;
                }
            }
            __syncthreads();
        }
        int win = hid[0];
        if (tid == 0) widx[r] = win;
        __syncthreads();
        if (id[0] == win) {  // winner removes its head (ids unique)
#pragma unroll
            for (int i = 0; i < KTOP - 1; i++) { v[i] = v[i + 1]; id[i] = id[i + 1]; }
            v[KTOP - 1] = -1e30f; id[KTOP - 1] = 1 << 30;
        }
    }
    __syncthreads();

    if (tid < NC) {
        float o = 0.f, tg = 0.f;
#pragma unroll
        for (int k = 0; k < KTOP; k++) {
            int n = widx[k];
            o += g_soft[n * NC + tid];
            tg += (g_predcls[n] == tid) ? 1.f : 0.f;
        }
        st[tid] = tg; so[tid] = o;
    }
    __syncthreads();
    if (tid == 0) {
        float ts = 0.f, os = 0.f;
#pragma unroll
        for (int c = 0; c < NC; c++) { ts += st[c]; os += so[c]; }
        ssum[0] = ts; ssum[1] = os;
    }
    __syncthreads();
    if (tid < NC) {
        out[(size_t)NB * NC + row * NC + tid] = st[tid] / (ssum[0] + EPS);
        out[(size_t)2 * NB * NC + row * NC + tid] = so[tid] / (ssum[1] + EPS);
    }
}

// ---------------- logits = TAU * zn @ centn^T ----------------
__global__ void k_logits(float* __restrict__ out) {
    __shared__ float sc[NC * ND];
    int tid = threadIdx.x;
    for (int i = tid; i < NC * ND; i += 256) sc[i] = g_centn[i];
    __syncthreads();
    int w = tid >> 5, lane = tid & 31;
    int row = blockIdx.x * 8 + w;
    float acc[NC];
#pragma unroll
    for (int c = 0; c < NC; c++) acc[c] = 0.f;
    const float* zr = g_zn + (size_t)row * ND;
#pragma unroll 4
    for (int i = 0; i < 16; i++) {
        float x = zr[lane + 32 * i];
#pragma unroll
        for (int c = 0; c < NC; c++) acc[c] += x * sc[c * ND + lane + 32 * i];
    }
#pragma unroll
    for (int c = 0; c < NC; c++) {
#pragma unroll
        for (int o = 16; o; o >>= 1) acc[c] += __shfl_xor_sync(0xffffffffu, acc[c], o);
    }
    if (lane == 0) {
#pragma unroll
        for (int c = 0; c < NC; c++) out[row * NC + c] = TAU * acc[c];
    }
}

// ---------------- launch ----------------
extern "C" void kernel_launch(void* const* d_in, const int* in_sizes, int n_in,
                              void* d_out, int out_size) {
    const float* z = (const float*)d_in[0];
    const float* supports = (const float*)d_in[1];
    const float* labels = (const float*)d_in[2];
    float* out = (float*)d_out;

    k_normalize<<<(NB + NS) / 8, 256>>>(z, supports);
    k_labcls<<<NS / 256, 256>>>(labels);
    k_colsum<<<NC, 256>>>(labels);
    k_cent_part<<<64, 512>>>(supports);
    k_cent_reduce<<<(NC * ND + 255) / 256, 256>>>();
    k_cent_norm<<<1, NC * 32>>>();
    k_templabels<<<NS / 8, 256>>>();
    dim3 gg(NS / BN, NB / BM);
    k_gemm<<<gg, 256>>>();
    k_topk<<<NB, 256>>>(out);
    k_logits<<<NB / 8, 256>>>(out);
}

// round 3
// speedup vs baseline: 2.1355x; 2.1355x over previous
#include <cuda_runtime.h>
#include <cuda_bf16.h>
#include <math.h>
#include <stdint.h>

// Problem constants
#define NB 2048     // queries
#define NS 16384    // supports
#define ND 512      // dim
#define NC 17       // classes
#define KTOP 8
#define TAU 10.0f
#define EPS 1e-12f

#define KTOT 1536   // expanded K: [hh | hm | mh] blocks of 512
#define GITERS 24   // KTOT / 64
#define GSTAGE 32768
#define GEMM_SMEM (3 * GSTAGE)

// ---------------- scratch (device globals; no runtime alloc) ----------------
__device__ float g_zn[NB * ND];            // normalized z
__device__ float g_sn[NS * ND];            // normalized supports
__device__ float g_cent[NC * ND];          // centroids
__device__ float g_centn[NC * ND];         // normalized centroids
__device__ float g_cnt[NC];                // label column sums
__device__ int   g_labcls[NS];             // argmax(labels) per support
__device__ int   g_predcls[NS];            // argmax(temp_labels) per support
__device__ float g_soft[NS * NC];          // softmax(temp_labels)
__device__ float g_part[128 * NC * ND];    // centroid partials
__device__ float g_cos[(size_t)NB * NS];   // query-support cosine (134 MB)

// expanded bf16 operands (K = 1536)
__device__ __align__(16) __nv_bfloat16 g_A2[(size_t)NB * KTOT];  // [Ah|Ah|Am]
__device__ __align__(16) __nv_bfloat16 g_B2[(size_t)NS * KTOT];  // [Bh|Bm|Bh]

// ---------------- PTX helpers ----------------
__device__ __forceinline__ uint32_t smem_u32(const void* p) {
    uint32_t a;
    asm("{ .reg .u64 t; cvta.to.shared.u64 t, %1; cvt.u32.u64 %0, t; }" : "=r"(a) : "l"(p));
    return a;
}
__device__ __forceinline__ void cp16(uint32_t saddr, const void* g) {
    asm volatile("cp.async.cg.shared.global [%0], [%1], 16;" :: "r"(saddr), "l"(g));
}
#define CP_COMMIT() asm volatile("cp.async.commit_group;" ::: "memory")

__device__ __forceinline__ void ldsm4(uint32_t* r, uint32_t addr) {
    asm volatile("ldmatrix.sync.aligned.m8n8.x4.shared.b16 {%0,%1,%2,%3}, [%4];"
        : "=r"(r[0]), "=r"(r[1]), "=r"(r[2]), "=r"(r[3]) : "r"(addr));
}
__device__ __forceinline__ void ldsm2(uint32_t* r, uint32_t addr) {
    asm volatile("ldmatrix.sync.aligned.m8n8.x2.shared.b16 {%0,%1}, [%2];"
        : "=r"(r[0]), "=r"(r[1]) : "r"(addr));
}
__device__ __forceinline__ void mma16816(float* d, const uint32_t* a, const uint32_t* b) {
    asm volatile(
        "mma.sync.aligned.m16n8k16.row.col.f32.bf16.bf16.f32 "
        "{%0,%1,%2,%3}, {%4,%5,%6,%7}, {%8,%9}, {%0,%1,%2,%3};"
        : "+f"(d[0]), "+f"(d[1]), "+f"(d[2]), "+f"(d[3])
        : "r"(a[0]), "r"(a[1]), "r"(a[2]), "r"(a[3]), "r"(b[0]), "r"(b[1]));
}
__device__ __forceinline__ uint32_t swz(uint32_t o) { return o ^ ((o >> 3) & 0x70); }

// ---------------- normalization + bf16 split into expanded layout ----------------
__global__ void k_normalize(const float* __restrict__ z, const float* __restrict__ sup) {
    int gw = (blockIdx.x * blockDim.x + threadIdx.x) >> 5;
    int lane = threadIdx.x & 31;
    if (gw >= NB + NS) return;
    const float* src;
    float* dst;
    __nv_bfloat16* e;
    bool isA = gw < NB;
    if (isA) {
        src = z + (size_t)gw * ND;
        dst = g_zn + (size_t)gw * ND;
        e = g_A2 + (size_t)gw * KTOT;
    } else {
        int r = gw - NB;
        src = sup + (size_t)r * ND;
        dst = g_sn + (size_t)r * ND;
        e = g_B2 + (size_t)r * KTOT;
    }
    float v[16];
    float ss = 0.f;
#pragma unroll
    for (int i = 0; i < 16; i++) {
        float x = src[lane + 32 * i];
        v[i] = x;
        ss += x * x;
    }
#pragma unroll
    for (int o = 16; o; o >>= 1) ss += __shfl_xor_sync(0xffffffffu, ss, o);
    float inv = 1.f / fmaxf(sqrtf(ss), EPS);
#pragma unroll
    for (int i = 0; i < 16; i++) {
        float x = v[i] * inv;
        int idx = lane + 32 * i;
        dst[idx] = x;
        __nv_bfloat16 h = __float2bfloat16(x);
        float r1 = x - __bfloat162float(h);
        __nv_bfloat16 m = __float2bfloat16(r1);
        if (isA) {          // A blocks: [Ah | Ah | Am]
            e[idx] = h; e[idx + 512] = h; e[idx + 1024] = m;
        } else {            // B blocks: [Bh | Bm | Bh]
            e[idx] = h; e[idx + 512] = m; e[idx + 1024] = h;
        }
    }
}

// ---------------- label argmax per support ----------------
__global__ void k_labcls(const float* __restrict__ labels) {
    int n = blockIdx.x * blockDim.x + threadIdx.x;
    if (n >= NS) return;
    const float* r = labels + n * NC;
    float m = r[0]; int mi = 0;
#pragma unroll
    for (int c = 1; c < NC; c++) { float x = r[c]; if (x > m) { m = x; mi = c; } }
    g_labcls[n] = mi;
}

// ---------------- label column sums ----------------
__global__ void k_colsum(const float* __restrict__ labels) {
    __shared__ float sh[256];
    int c = blockIdx.x, tid = threadIdx.x;
    float s = 0.f;
    for (int n = tid; n < NS; n += 256) s += labels[n * NC + c];
    sh[tid] = s;
    __syncthreads();
    for (int st = 128; st; st >>= 1) {
        if (tid < st) sh[tid] += sh[tid + st];
        __syncthreads();
    }
    if (tid == 0) g_cnt[c] = sh[0];
}

// ---------------- centroid partials (atomic-free) ----------------
__global__ void k_cent_part(const float* __restrict__ sup) {
    __shared__ float sp[NC * ND];
    int tid = threadIdx.x;
    for (int i = tid; i < NC * ND; i += 512) sp[i] = 0.f;
    __syncthreads();
    int n0 = blockIdx.x * 128;
    for (int n = 0; n < 128; n++) {
        int c = g_labcls[n0 + n];
        sp[c * ND + tid] += sup[(size_t)(n0 + n) * ND + tid];
    }
    __syncthreads();
    float* dst = g_part + (size_t)blockIdx.x * NC * ND;
    for (int i = tid; i < NC * ND; i += 512) dst[i] = sp[i];
}

__global__ void k_cent_reduce() {
    int i = blockIdx.x * blockDim.x + threadIdx.x;
    if (i >= NC * ND) return;
    float s = 0.f;
    for (int b = 0; b < 128; b++) s += g_part[(size_t)b * NC * ND + i];
    int c = i / ND;
    g_cent[i] = s / (g_cnt[c] + EPS);
}

__global__ void k_cent_norm() {
    int w = threadIdx.x >> 5, lane = threadIdx.x & 31;
    if (w >= NC) return;
    float v[16];
    float ss = 0.f;
#pragma unroll
    for (int i = 0; i < 16; i++) {
        float x = g_cent[w * ND + lane + 32 * i];
        v[i] = x; ss += x * x;
    }
#pragma unroll
    for (int o = 16; o; o >>= 1) ss += __shfl_xor_sync(0xffffffffu, ss, o);
    float inv = 1.f / fmaxf(sqrtf(ss), EPS);
#pragma unroll
    for (int i = 0; i < 16; i++) g_centn[w * ND + lane + 32 * i] = v[i] * inv;
}

// ---------------- temp_labels: argmax class + softmax per support ----------------
__global__ void k_templabels() {
    __shared__ float sc[NC * ND];
    int tid = threadIdx.x;
    for (int i = tid; i < NC * ND; i += 256) sc[i] = g_centn[i];
    __syncthreads();
    int w = tid >> 5, lane = tid & 31;
    int row = blockIdx.x * 8 + w;
    float acc[NC];
#pragma unroll
    for (int c = 0; c < NC; c++) acc[c] = 0.f;
    const float* sr = g_sn + (size_t)row * ND;
#pragma unroll 4
    for (int i = 0; i < 16; i++) {
        float x = sr[lane + 32 * i];
#pragma unroll
        for (int c = 0; c < NC; c++) acc[c] += x * sc[c * ND + lane + 32 * i];
    }
#pragma unroll
    for (int c = 0; c < NC; c++) {
#pragma unroll
        for (int o = 16; o; o >>= 1) acc[c] += __shfl_xor_sync(0xffffffffu, acc[c], o);
    }
    if (lane == 0) {
        float t[NC];
        float m = -1e30f; int mi = 0;
#pragma unroll
        for (int c = 0; c < NC; c++) {
            t[c] = TAU * acc[c];
            if (t[c] > m) { m = t[c]; mi = c; }
        }
        float s = 0.f;
#pragma unroll
        for (int c = 0; c < NC; c++) { t[c] = expf(t[c] - m); s += t[c]; }
#pragma unroll
        for (int c = 0; c < NC; c++) g_soft[row * NC + c] = t[c] / s;
        g_predcls[row] = mi;
    }
}

// ---------------- HMMA GEMM: g_cos = A2 @ B2^T  (bf16, K=1536, fp32 accum) --------
__device__ __forceinline__ void g_load_stage(uint32_t sb, int buf, int k0,
                                             int brow, int bcol, int tid) {
    uint32_t abase = sb + buf * GSTAGE;
    uint32_t bbase = abase + 16384;
#pragma unroll
    for (int i = 0; i < 4; i++) {
        int u = tid + 256 * i;
        int r = u >> 3, sg = u & 7;
        cp16(abase + swz(r * 128 + sg * 16),
             g_A2 + (size_t)(brow + r) * KTOT + k0 + sg * 8);
    }
#pragma unroll
    for (int i = 0; i < 4; i++) {
        int u = tid + 256 * i;
        int r = u >> 3, sg = u & 7;
        cp16(bbase + swz(r * 128 + sg * 16),
             g_B2 + (size_t)(bcol + r) * KTOT + k0 + sg * 8);
    }
}

__global__ __launch_bounds__(256, 2) void k_gemm_mma() {
    extern __shared__ __align__(1024) char smem[];
    uint32_t sb = smem_u32(smem);
    const int tid = threadIdx.x;
    const int brow = blockIdx.y * 128;
    const int bcol = blockIdx.x * 128;
    const int w = tid >> 5, lane = tid & 31;
    const int wm = (w >> 2) * 64;   // 2 warps in m
    const int wn = (w & 3) * 32;    // 4 warps in n

    float acc[4][4][4];
#pragma unroll
    for (int a = 0; a < 4; a++)
#pragma unroll
        for (int b = 0; b < 4; b++)
#pragma unroll
            for (int c = 0; c < 4; c++) acc[a][b][c] = 0.f;

    g_load_stage(sb, 0, 0, brow, bcol, tid);
    CP_COMMIT();
    g_load_stage(sb, 1, 64, brow, bcol, tid);
    CP_COMMIT();

#pragma unroll 1
    for (int it = 0; it < GITERS; it++) {
        asm volatile("cp.async.wait_group 1;" ::: "memory");
        __syncthreads();
        if (it + 2 < GITERS)
            g_load_stage(sb, (it + 2) % 3, (it + 2) * 64, brow, bcol, tid);
        CP_COMMIT();  // empty groups keep the wait_group count uniform

        uint32_t As = sb + (it % 3) * GSTAGE;
        uint32_t Bs = As + 16384;
#pragma unroll
        for (int ks = 0; ks < 4; ks++) {
            uint32_t af[4][4], bf[4][2];
#pragma unroll
            for (int mt = 0; mt < 4; mt++) {
                uint32_t row = wm + mt * 16 + (lane & 15);
                uint32_t cb = ks * 32 + ((lane >> 4) << 4);
                ldsm4(af[mt], As + swz(row * 128 + cb));
            }
#pragma unroll
            for (int nt = 0; nt < 4; nt++) {
                uint32_t row = wn + nt * 8 + (lane & 7);
                uint32_t cb = ks * 32 + (((lane >> 3) & 1) << 4);
                ldsm2(bf[nt], Bs + swz(row * 128 + cb));
            }
#pragma unroll
            for (int mt = 0; mt < 4; mt++)
#pragma unroll
                for (int nt = 0; nt < 4; nt++)
                    mma16816(acc[mt][nt], af[mt], bf[nt]);
        }
    }

    // epilogue: write fp32 cosines
#pragma unroll
    for (int mt = 0; mt < 4; mt++) {
        int r0 = brow + wm + mt * 16 + (lane >> 2);
#pragma unroll
        for (int nt = 0; nt < 4; nt++) {
            int c0 = bcol + wn + nt * 8 + (lane & 3) * 2;
            *(float2*)&g_cos[(size_t)r0 * NS + c0] =
                make_float2(acc[mt][nt][0], acc[mt][nt][1]);
            *(float2*)&g_cos[(size_t)(r0 + 8) * NS + c0] =
                make_float2(acc[mt][nt][2], acc[mt][nt][3]);
        }
    }
}

// ---------------- per-row top-8 + targets/outputs ----------------
__global__ void k_topk(float* __restrict__ out) {
    __shared__ float hv[256];
    __shared__ int hid[256];
    __shared__ int widx[KTOP];
    __shared__ float st[NC], so[NC], ssum[2];
    const int row = blockIdx.x;
    const int tid = threadIdx.x;
    const float* W = g_cos + (size_t)row * NS;

    float v[KTOP];
    int id[KTOP];
#pragma unroll
    for (int i = 0; i < KTOP; i++) { v[i] = -1e30f; id[i] = 1 << 30; }

    for (int t = 0; t < NS / 256; t++) {
        int j = tid + (t << 8);
        float x = W[j];
        if (x > v[KTOP - 1]) {
            v[KTOP - 1] = x; id[KTOP - 1] = j;
#pragma unroll
            for (int i = KTOP - 1; i >= 1; i--) {
                if (v[i] > v[i - 1]) {
                    float tv = v[i]; v[i] = v[i - 1]; v[i - 1] = tv;
                    int ti = id[i]; id[i] = id[i - 1]; id[i - 1] = ti;
                }
            }
        }
    }

    for (int r = 0; r < KTOP; r++) {
        hv[tid] = v[0];
        hid[tid] = id[0];
        __syncthreads();
        for (int s = 128; s; s >>= 1) {
            if (tid < s) {
                float v2 = hv[tid + s]; int i2 = hid[tid + s];
                if (v2 > hv[tid] || (v2 == hv[tid] && i2 < hid[tid])) {
                    hv[tid] = v2; hid[tid] = i2;
                }
            }
            __syncthreads();
        }
        int win = hid[0];
        if (tid == 0) widx[r] = win;
        __syncthreads();
        if (id[0] == win) {
#pragma unroll
            for (int i = 0; i < KTOP - 1; i++) { v[i] = v[i + 1]; id[i] = id[i + 1]; }
            v[KTOP - 1] = -1e30f; id[KTOP - 1] = 1 << 30;
        }
    }
    __syncthreads();

    if (tid < NC) {
        float o = 0.f, tg = 0.f;
#pragma unroll
        for (int k = 0; k < KTOP; k++) {
            int n = widx[k];
            o += g_soft[n * NC + tid];
            tg += (g_predcls[n] == tid) ? 1.f : 0.f;
        }
        st[tid] = tg; so[tid] = o;
    }
    __syncthreads();
    if (tid == 0) {
        float ts = 0.f, os = 0.f;
#pragma unroll
        for (int c = 0; c < NC; c++) { ts += st[c]; os += so[c]; }
        ssum[0] = ts; ssum[1] = os;
    }
    __syncthreads();
    if (tid < NC) {
        out[(size_t)NB * NC + row * NC + tid] = st[tid] / (ssum[0] + EPS);
        out[(size_t)2 * NB * NC + row * NC + tid] = so[tid] / (ssum[1] + EPS);
    }
}

// ---------------- logits = TAU * zn @ centn^T ----------------
__global__ void k_logits(float* __restrict__ out) {
    __shared__ float sc[NC * ND];
    int tid = threadIdx.x;
    for (int i = tid; i < NC * ND; i += 256) sc[i] = g_centn[i];
    __syncthreads();
    int w = tid >> 5, lane = tid & 31;
    int row = blockIdx.x * 8 + w;
    float acc[NC];
#pragma unroll
    for (int c = 0; c < NC; c++) acc[c] = 0.f;
    const float* zr = g_zn + (size_t)row * ND;
#pragma unroll 4
    for (int i = 0; i < 16; i++) {
        float x = zr[lane + 32 * i];
#pragma unroll
        for (int c = 0; c < NC; c++) acc[c] += x * sc[c * ND + lane + 32 * i];
    }
#pragma unroll
    for (int c = 0; c < NC; c++) {
#pragma unroll
        for (int o = 16; o; o >>= 1) acc[c] += __shfl_xor_sync(0xffffffffu, acc[c], o);
    }
    if (lane == 0) {
#pragma unroll
        for (int c = 0; c < NC; c++) out[row * NC + c] = TAU * acc[c];
    }
}

// ---------------- launch ----------------
extern "C" void kernel_launch(void* const* d_in, const int* in_sizes, int n_in,
                              void* d_out, int out_size) {
    const float* z = (const float*)d_in[0];
    const float* supports = (const float*)d_in[1];
    const float* labels = (const float*)d_in[2];
    float* out = (float*)d_out;

    cudaFuncSetAttribute(k_gemm_mma, cudaFuncAttributeMaxDynamicSharedMemorySize,
                         GEMM_SMEM);

    k_normalize<<<(NB + NS) / 8, 256>>>(z, supports);
    k_labcls<<<NS / 256, 256>>>(labels);
    k_colsum<<<NC, 256>>>(labels);
    k_cent_part<<<128, 512>>>(supports);
    k_cent_reduce<<<(NC * ND + 255) / 256, 256>>>();
    k_cent_norm<<<1, NC * 32>>>();
    k_templabels<<<NS / 8, 256>>>();
    dim3 gg(NS / 128, NB / 128);
    k_gemm_mma<<<gg, 256, GEMM_SMEM>>>();
    k_topk<<<NB, 256>>>(out);
    k_logits<<<NB / 8, 256>>>(out);
}

// round 4
// speedup vs baseline: 2.5675x; 1.2023x over previous
#include <cuda_runtime.h>
#include <cuda_bf16.h>
#include <math.h>
#include <stdint.h>

// Problem constants
#define NB 2048     // queries
#define NS 16384    // supports
#define ND 512      // dim
#define NC 17       // classes
#define KTOP 8
#define KCAND 16    // candidates kept from approximate ranking
#define TAU 10.0f
#define EPS 1e-12f

#define GITERS 8        // ND / 64
#define GSTAGE 32768
#define GEMM_SMEM (3 * GSTAGE)
#define NPART 512       // centroid partial chunks

// ---------------- scratch (device globals; no runtime alloc) ----------------
__device__ float g_zn[NB * ND];            // normalized z (fp32, exact)
__device__ float g_sn[NS * ND];            // normalized supports (fp32, exact)
__device__ float g_XX[NB];                 // sum(zn^2) per row
__device__ float g_YY[NS];                 // sum(sn^2) per support
__device__ float g_cent[NC * ND];
__device__ float g_centn[NC * ND];
__device__ float g_cnt[NC];
__device__ int   g_labcls[NS];
__device__ int   g_predcls[NS];
__device__ float g_soft[NS * NC];
__device__ float g_part[NPART * NC * ND];
__device__ __align__(16) __nv_bfloat16 g_Ah[NB * ND];   // bf16(zn)
__device__ __align__(16) __nv_bfloat16 g_Bh[NS * ND];   // bf16(sn)
__device__ __align__(16) __nv_bfloat16 g_score[(size_t)NB * NS]; // approx cos (64MB)

// ---------------- PTX helpers ----------------
__device__ __forceinline__ uint32_t smem_u32(const void* p) {
    uint32_t a;
    asm("{ .reg .u64 t; cvta.to.shared.u64 t, %1; cvt.u32.u64 %0, t; }" : "=r"(a) : "l"(p));
    return a;
}
__device__ __forceinline__ void cp16(uint32_t saddr, const void* g) {
    asm volatile("cp.async.cg.shared.global [%0], [%1], 16;" :: "r"(saddr), "l"(g));
}
#define CP_COMMIT() asm volatile("cp.async.commit_group;" ::: "memory")

__device__ __forceinline__ void ldsm4(uint32_t* r, uint32_t addr) {
    asm volatile("ldmatrix.sync.aligned.m8n8.x4.shared.b16 {%0,%1,%2,%3}, [%4];"
        : "=r"(r[0]), "=r"(r[1]), "=r"(r[2]), "=r"(r[3]) : "r"(addr));
}
__device__ __forceinline__ void ldsm2(uint32_t* r, uint32_t addr) {
    asm volatile("ldmatrix.sync.aligned.m8n8.x2.shared.b16 {%0,%1}, [%2];"
        : "=r"(r[0]), "=r"(r[1]) : "r"(addr));
}
__device__ __forceinline__ void mma16816(float* d, const uint32_t* a, const uint32_t* b) {
    asm volatile(
        "mma.sync.aligned.m16n8k16.row.col.f32.bf16.bf16.f32 "
        "{%0,%1,%2,%3}, {%4,%5,%6,%7}, {%8,%9}, {%0,%1,%2,%3};"
        : "+f"(d[0]), "+f"(d[1]), "+f"(d[2]), "+f"(d[3])
        : "r"(a[0]), "r"(a[1]), "r"(a[2]), "r"(a[3]), "r"(b[0]), "r"(b[1]));
}
__device__ __forceinline__ uint32_t swz(uint32_t o) { return o ^ ((o >> 3) & 0x70); }

// ---------------- normalization + bf16 hi + self-dot ----------------
__global__ void k_normalize(const float* __restrict__ z, const float* __restrict__ sup) {
    int gw = (blockIdx.x * blockDim.x + threadIdx.x) >> 5;
    int lane = threadIdx.x & 31;
    if (gw >= NB + NS) return;
    const float* src;
    float* dst;
    __nv_bfloat16* eh;
    float* selfdot;
    bool isA = gw < NB;
    int r = isA ? gw : gw - NB;
    if (isA) { src = z + (size_t)r * ND; dst = g_zn + (size_t)r * ND; eh = g_Ah + (size_t)r * ND; selfdot = g_XX + r; }
    else     { src = sup + (size_t)r * ND; dst = g_sn + (size_t)r * ND; eh = g_Bh + (size_t)r * ND; selfdot = g_YY + r; }
    float v[16];
    float ss = 0.f;
#pragma unroll
    for (int i = 0; i < 16; i++) {
        float x = src[lane + 32 * i];
        v[i] = x;
        ss += x * x;
    }
#pragma unroll
    for (int o = 16; o; o >>= 1) ss += __shfl_xor_sync(0xffffffffu, ss, o);
    float inv = 1.f / fmaxf(sqrtf(ss), EPS);
    float nn = 0.f;
#pragma unroll
    for (int i = 0; i < 16; i++) {
        float x = v[i] * inv;
        int idx = lane + 32 * i;
        dst[idx] = x;
        eh[idx] = __float2bfloat16(x);
        nn += x * x;
    }
#pragma unroll
    for (int o = 16; o; o >>= 1) nn += __shfl_xor_sync(0xffffffffu, nn, o);
    if (lane == 0) *selfdot = nn;
}

// ---------------- label argmax per support ----------------
__global__ void k_labcls(const float* __restrict__ labels) {
    int n = blockIdx.x * blockDim.x + threadIdx.x;
    if (n >= NS) return;
    const float* r = labels + n * NC;
    float m = r[0]; int mi = 0;
#pragma unroll
    for (int c = 1; c < NC; c++) { float x = r[c]; if (x > m) { m = x; mi = c; } }
    g_labcls[n] = mi;
}

// ---------------- label column sums ----------------
__global__ void k_colsum(const float* __restrict__ labels) {
    __shared__ float sh[256];
    int c = blockIdx.x, tid = threadIdx.x;
    float s = 0.f;
    for (int n = tid; n < NS; n += 256) s += labels[n * NC + c];
    sh[tid] = s;
    __syncthreads();
    for (int st = 128; st; st >>= 1) {
        if (tid < st) sh[tid] += sh[tid + st];
        __syncthreads();
    }
    if (tid == 0) g_cnt[c] = sh[0];
}

// ---------------- centroid partials (atomic-free, 512 chunks x 32 rows) ----------
__global__ void k_cent_part(const float* __restrict__ sup) {
    __shared__ float sp[NC * ND];
    int tid = threadIdx.x;  // 512 threads, one per dim
    for (int i = tid; i < NC * ND; i += 512) sp[i] = 0.f;
    __syncthreads();
    int n0 = blockIdx.x * 32;
    for (int n = 0; n < 32; n++) {
        int c = g_labcls[n0 + n];
        sp[c * ND + tid] += sup[(size_t)(n0 + n) * ND + tid];
    }
    __syncthreads();
    float* dst = g_part + (size_t)blockIdx.x * NC * ND;
    for (int i = tid; i < NC * ND; i += 512) dst[i] = sp[i];
}

__global__ void k_cent_reduce() {
    int i = blockIdx.x * blockDim.x + threadIdx.x;
    if (i >= NC * ND) return;
    float s = 0.f;
    for (int b = 0; b < NPART; b++) s += g_part[(size_t)b * NC * ND + i];
    int c = i / ND;
    g_cent[i] = s / (g_cnt[c] + EPS);
}

__global__ void k_cent_norm() {
    int w = threadIdx.x >> 5, lane = threadIdx.x & 31;
    if (w >= NC) return;
    float v[16];
    float ss = 0.f;
#pragma unroll
    for (int i = 0; i < 16; i++) {
        float x = g_cent[w * ND + lane + 32 * i];
        v[i] = x; ss += x * x;
    }
#pragma unroll
    for (int o = 16; o; o >>= 1) ss += __shfl_xor_sync(0xffffffffu, ss, o);
    float inv = 1.f / fmaxf(sqrtf(ss), EPS);
#pragma unroll
    for (int i = 0; i < 16; i++) g_centn[w * ND + lane + 32 * i] = v[i] * inv;
}

// ---------------- temp_labels: argmax class + softmax per support ----------------
__global__ void k_templabels() {
    __shared__ float sc[NC * ND];
    int tid = threadIdx.x;
    for (int i = tid; i < NC * ND; i += 256) sc[i] = g_centn[i];
    __syncthreads();
    int w = tid >> 5, lane = tid & 31;
    int row = blockIdx.x * 8 + w;
    float acc[NC];
#pragma unroll
    for (int c = 0; c < NC; c++) acc[c] = 0.f;
    const float* sr = g_sn + (size_t)row * ND;
#pragma unroll 4
    for (int i = 0; i < 16; i++) {
        float x = sr[lane + 32 * i];
#pragma unroll
        for (int c = 0; c < NC; c++) acc[c] += x * sc[c * ND + lane + 32 * i];
    }
#pragma unroll
    for (int c = 0; c < NC; c++) {
#pragma unroll
        for (int o = 16; o; o >>= 1) acc[c] += __shfl_xor_sync(0xffffffffu, acc[c], o);
    }
    if (lane == 0) {
        float t[NC];
        float m = -1e30f; int mi = 0;
#pragma unroll
        for (int c = 0; c < NC; c++) {
            t[c] = TAU * acc[c];
            if (t[c] > m) { m = t[c]; mi = c; }
        }
        float s = 0.f;
#pragma unroll
        for (int c = 0; c < NC; c++) { t[c] = expf(t[c] - m); s += t[c]; }
#pragma unroll
        for (int c = 0; c < NC; c++) g_soft[row * NC + c] = t[c] / s;
        g_predcls[row] = mi;
    }
}

// ---------------- HMMA GEMM (approx): g_score = bf16(Ah @ Bh^T), K=512 ----------
__device__ __forceinline__ void g_load_stage(uint32_t sb, int buf, int k0,
                                             int brow, int bcol, int tid) {
    uint32_t abase = sb + buf * GSTAGE;
    uint32_t bbase = abase + 16384;
#pragma unroll
    for (int i = 0; i < 4; i++) {
        int u = tid + 256 * i;
        int r = u >> 3, sg = u & 7;
        cp16(abase + swz(r * 128 + sg * 16),
             g_Ah + (size_t)(brow + r) * ND + k0 + sg * 8);
    }
#pragma unroll
    for (int i = 0; i < 4; i++) {
        int u = tid + 256 * i;
        int r = u >> 3, sg = u & 7;
        cp16(bbase + swz(r * 128 + sg * 16),
             g_Bh + (size_t)(bcol + r) * ND + k0 + sg * 8);
    }
}

__global__ __launch_bounds__(256, 2) void k_gemm_mma() {
    extern __shared__ __align__(1024) char smem[];
    uint32_t sb = smem_u32(smem);
    const int tid = threadIdx.x;
    const int brow = blockIdx.y * 128;
    const int bcol = blockIdx.x * 128;
    const int w = tid >> 5, lane = tid & 31;
    const int wm = (w >> 2) * 64;   // 2 warps in m
    const int wn = (w & 3) * 32;    // 4 warps in n

    float acc[4][4][4];
#pragma unroll
    for (int a = 0; a < 4; a++)
#pragma unroll
        for (int b = 0; b < 4; b++)
#pragma unroll
            for (int c = 0; c < 4; c++) acc[a][b][c] = 0.f;

    g_load_stage(sb, 0, 0, brow, bcol, tid);
    CP_COMMIT();
    g_load_stage(sb, 1, 64, brow, bcol, tid);
    CP_COMMIT();

#pragma unroll 1
    for (int it = 0; it < GITERS; it++) {
        asm volatile("cp.async.wait_group 1;" ::: "memory");
        __syncthreads();
        if (it + 2 < GITERS)
            g_load_stage(sb, (it + 2) % 3, (it + 2) * 64, brow, bcol, tid);
        CP_COMMIT();

        uint32_t As = sb + (it % 3) * GSTAGE;
        uint32_t Bs = As + 16384;
#pragma unroll
        for (int ks = 0; ks < 4; ks++) {
            uint32_t af[4][4], bf[4][2];
#pragma unroll
            for (int mt = 0; mt < 4; mt++) {
                uint32_t row = wm + mt * 16 + (lane & 15);
                uint32_t cb = ks * 32 + ((lane >> 4) << 4);
                ldsm4(af[mt], As + swz(row * 128 + cb));
            }
#pragma unroll
            for (int nt = 0; nt < 4; nt++) {
                uint32_t row = wn + nt * 8 + (lane & 7);
                uint32_t cb = ks * 32 + (((lane >> 3) & 1) << 4);
                ldsm2(bf[nt], Bs + swz(row * 128 + cb));
            }
#pragma unroll
            for (int mt = 0; mt < 4; mt++)
#pragma unroll
                for (int nt = 0; nt < 4; nt++)
                    mma16816(acc[mt][nt], af[mt], bf[nt]);
        }
    }

    // epilogue: bf16 approximate scores
#pragma unroll
    for (int mt = 0; mt < 4; mt++) {
        int r0 = brow + wm + mt * 16 + (lane >> 2);
#pragma unroll
        for (int nt = 0; nt < 4; nt++) {
            int c0 = bcol + wn + nt * 8 + (lane & 3) * 2;
            __nv_bfloat162 p0 = __floats2bfloat162_rn(acc[mt][nt][0], acc[mt][nt][1]);
            __nv_bfloat162 p1 = __floats2bfloat162_rn(acc[mt][nt][2], acc[mt][nt][3]);
            *(__nv_bfloat162*)&g_score[(size_t)r0 * NS + c0] = p0;
            *(__nv_bfloat162*)&g_score[(size_t)(r0 + 8) * NS + c0] = p1;
        }
    }
}

// ---------------- per-row top-16 candidates -> exact fp32 rescore -> top-8 ------
__global__ void k_topk(float* __restrict__ out) {
    __shared__ float zrow[ND];
    __shared__ float hv[256];
    __shared__ int hid[256];
    __shared__ int widx[KCAND];
    __shared__ float cdist[KCAND];
    __shared__ int sel[KTOP];
    __shared__ float st[NC], so[NC], ssum[2];
    const int row = blockIdx.x;
    const int tid = threadIdx.x;

    // cache query row (exact fp32)
    zrow[tid] = g_zn[(size_t)row * ND + tid];
    zrow[tid + 256] = g_zn[(size_t)row * ND + tid + 256];

    const __nv_bfloat162* W2 = (const __nv_bfloat162*)(g_score + (size_t)row * NS);

    float v[KTOP];
    int id[KTOP];
#pragma unroll
    for (int i = 0; i < KTOP; i++) { v[i] = -1e30f; id[i] = 1 << 30; }

    // scan approximate scores (bf16x2), per-thread sorted top-8
    for (int t = 0; t < NS / 512; t++) {
        int j2 = tid + (t << 8);
        __nv_bfloat162 p = W2[j2];
        float x0 = __bfloat162float(p.x);
        float x1 = __bfloat162float(p.y);
#pragma unroll
        for (int h = 0; h < 2; h++) {
            float x = h ? x1 : x0;
            int j = 2 * j2 + h;
            if (x > v[KTOP - 1]) {
                v[KTOP - 1] = x; id[KTOP - 1] = j;
#pragma unroll
                for (int i = KTOP - 1; i >= 1; i--) {
                    if (v[i] > v[i - 1]) {
                        float tv = v[i]; v[i] = v[i - 1]; v[i - 1] = tv;
                        int ti = id[i]; id[i] = id[i - 1]; id[i - 1] = ti;
                    }
                }
            }
        }
    }

    // 16 tournament rounds -> candidate indices
    for (int r = 0; r < KCAND; r++) {
        hv[tid] = v[0];
        hid[tid] = id[0];
        __syncthreads();
        for (int s = 128; s; s >>= 1) {
            if (tid < s) {
                float v2 = hv[tid + s]; int i2 = hid[tid + s];
                if (v2 > hv[tid] || (v2 == hv[tid] && i2 < hid[tid])) {
                    hv[tid] = v2; hid[tid] = i2;
                }
            }
            __syncthreads();
        }
        int win = hid[0];
        if (tid == 0) widx[r] = win;
        __syncthreads();
        if (id[0] == win) {
#pragma unroll
            for (int i = 0; i < KTOP - 1; i++) { v[i] = v[i + 1]; id[i] = id[i + 1]; }
            v[KTOP - 1] = -1e30f; id[KTOP - 1] = 1 << 30;
        }
    }
    __syncthreads();

    // exact fp32 rescore of the 16 candidates: dist = XX + YY - 2*dot
    {
        int w = tid >> 5, lane = tid & 31;
        float XXr = g_XX[row];
        for (int cand = w; cand < KCAND; cand += 8) {
            int n = widx[cand];
            const float* sr = g_sn + (size_t)n * ND;
            float d = 0.f;
#pragma unroll 4
            for (int i = 0; i < 16; i++) d += zrow[lane + 32 * i] * sr[lane + 32 * i];
#pragma unroll
            for (int o = 16; o; o >>= 1) d += __shfl_xor_sync(0xffffffffu, d, o);
            if (lane == 0) cdist[cand] = XXr + g_YY[n] - 2.f * d;
        }
    }
    __syncthreads();

    // select 8 smallest dist (tie -> lower support index)
    if (tid == 0) {
        unsigned used = 0;
#pragma unroll
        for (int k = 0; k < KTOP; k++) {
            float bd = 1e30f; int bi = -1, bn = 1 << 30;
#pragma unroll
            for (int c = 0; c < KCAND; c++) {
                if (used & (1u << c)) continue;
                float dc = cdist[c]; int nc_ = widx[c];
                if (dc < bd || (dc == bd && nc_ < bn)) { bd = dc; bi = c; bn = nc_; }
            }
            used |= 1u << bi;
            sel[k] = bn;
        }
    }
    __syncthreads();

    if (tid < NC) {
        float o = 0.f, tg = 0.f;
#pragma unroll
        for (int k = 0; k < KTOP; k++) {
            int n = sel[k];
            o += g_soft[n * NC + tid];
            tg += (g_predcls[n] == tid) ? 1.f : 0.f;
        }
        st[tid] = tg; so[tid] = o;
    }
    __syncthreads();
    if (tid == 0) {
        float ts = 0.f, os = 0.f;
#pragma unroll
        for (int c = 0; c < NC; c++) { ts += st[c]; os += so[c]; }
        ssum[0] = ts; ssum[1] = os;
    }
    __syncthreads();
    if (tid < NC) {
        out[(size_t)NB * NC + row * NC + tid] = st[tid] / (ssum[0] + EPS);
        out[(size_t)2 * NB * NC + row * NC + tid] = so[tid] / (ssum[1] + EPS);
    }
}

// ---------------- logits = TAU * zn @ centn^T ----------------
__global__ void k_logits(float* __restrict__ out) {
    __shared__ float sc[NC * ND];
    int tid = threadIdx.x;
    for (int i = tid; i < NC * ND; i += 256) sc[i] = g_centn[i];
    __syncthreads();
    int w = tid >> 5, lane = tid & 31;
    int row = blockIdx.x * 8 + w;
    float acc[NC];
#pragma unroll
    for (int c = 0; c < NC; c++) acc[c] = 0.f;
    const float* zr = g_zn + (size_t)row * ND;
#pragma unroll 4
    for (int i = 0; i < 16; i++) {
        float x = zr[lane + 32 * i];
#pragma unroll
        for (int c = 0; c < NC; c++) acc[c] += x * sc[c * ND + lane + 32 * i];
    }
#pragma unroll
    for (int c = 0; c < NC; c++) {
#pragma unroll
        for (int o = 16; o; o >>= 1) acc[c] += __shfl_xor_sync(0xffffffffu, acc[c], o);
    }
    if (lane == 0) {
#pragma unroll
        for (int c = 0; c < NC; c++) out[row * NC + c] = TAU * acc[c];
    }
}

// ---------------- launch ----------------
extern "C" void kernel_launch(void* const* d_in, const int* in_sizes, int n_in,
                              void* d_out, int out_size) {
    const float* z = (const float*)d_in[0];
    const float* supports = (const float*)d_in[1];
    const float* labels = (const float*)d_in[2];
    float* out = (float*)d_out;

    cudaFuncSetAttribute(k_gemm_mma, cudaFuncAttributeMaxDynamicSharedMemorySize,
                         GEMM_SMEM);

    k_normalize<<<(NB + NS) / 8, 256>>>(z, supports);
    k_labcls<<<NS / 256, 256>>>(labels);
    k_colsum<<<NC, 256>>>(labels);
    k_cent_part<<<NPART, 512>>>(supports);
    k_cent_reduce<<<(NC * ND + 255) / 256, 256>>>();
    k_cent_norm<<<1, NC * 32>>>();
    k_templabels<<<NS / 8, 256>>>();
    dim3 gg(NS / 128, NB / 128);
    k_gemm_mma<<<gg, 256, GEMM_SMEM>>>();
    k_topk<<<NB, 256>>>(out);
    k_logits<<<NB / 8, 256>>>(out);
}

// round 5
// speedup vs baseline: 2.6998x; 1.0515x over previous
#include <cuda_runtime.h>
#include <cuda_bf16.h>
#include <math.h>
#include <stdint.h>

typedef unsigned long long u64;
typedef unsigned int u32;

// Problem constants
#define NB 2048     // queries
#define NS 16384    // supports
#define ND 512      // dim
#define NC 17       // classes
#define KTOP 8
#define KCAND 16    // candidates rescored exactly
#define TAU 10.0f
#define EPS 1e-12f

#define GITERS 8        // ND / 64
#define GSTAGE 32768
#define GEMM_SMEM (3 * GSTAGE)   // 96 KB; also reused for 128x132 fp32 tile (67.6 KB)
#define NTILE 128       // NS / 128 column tiles per row
#define NPART 512       // centroid partial chunks

// ---------------- scratch (device globals; no runtime alloc) ----------------
__device__ float g_zn[NB * ND];            // normalized z (fp32, exact)
__device__ float g_sn[NS * ND];            // normalized supports (fp32, exact)
__device__ float g_XX[NB];                 // sum(zn^2) per row
__device__ float g_YY[NS];                 // sum(sn^2) per support
__device__ float g_cent[NC * ND];
__device__ float g_centn[NC * ND];
__device__ float g_cnt[NC];
__device__ int   g_labcls[NS];
__device__ int   g_predcls[NS];
__device__ float g_soft[NS * NC];
__device__ float g_part[NPART * NC * ND];
__device__ __align__(16) __nv_bfloat16 g_Ah[NB * ND];   // bf16(zn)
__device__ __align__(16) __nv_bfloat16 g_Bh[NS * ND];   // bf16(sn)
__device__ u64 g_cand[(size_t)NB * NTILE * KTOP];       // per-tile top-8 (16 MB)

// ---------------- PTX helpers ----------------
__device__ __forceinline__ uint32_t smem_u32(const void* p) {
    uint32_t a;
    asm("{ .reg .u64 t; cvta.to.shared.u64 t, %1; cvt.u32.u64 %0, t; }" : "=r"(a) : "l"(p));
    return a;
}
__device__ __forceinline__ void cp16(uint32_t saddr, const void* g) {
    asm volatile("cp.async.cg.shared.global [%0], [%1], 16;" :: "r"(saddr), "l"(g));
}
#define CP_COMMIT() asm volatile("cp.async.commit_group;" ::: "memory")

__device__ __forceinline__ void ldsm4(uint32_t* r, uint32_t addr) {
    asm volatile("ldmatrix.sync.aligned.m8n8.x4.shared.b16 {%0,%1,%2,%3}, [%4];"
        : "=r"(r[0]), "=r"(r[1]), "=r"(r[2]), "=r"(r[3]) : "r"(addr));
}
__device__ __forceinline__ void ldsm2(uint32_t* r, uint32_t addr) {
    asm volatile("ldmatrix.sync.aligned.m8n8.x2.shared.b16 {%0,%1}, [%2];"
        : "=r"(r[0]), "=r"(r[1]) : "r"(addr));
}
__device__ __forceinline__ void mma16816(float* d, const uint32_t* a, const uint32_t* b) {
    asm volatile(
        "mma.sync.aligned.m16n8k16.row.col.f32.bf16.bf16.f32 "
        "{%0,%1,%2,%3}, {%4,%5,%6,%7}, {%8,%9}, {%0,%1,%2,%3};"
        : "+f"(d[0]), "+f"(d[1]), "+f"(d[2]), "+f"(d[3])
        : "r"(a[0]), "r"(a[1]), "r"(a[2]), "r"(a[3]), "r"(b[0]), "r"(b[1]));
}
__device__ __forceinline__ uint32_t swz(uint32_t o) { return o ^ ((o >> 3) & 0x70); }

// monotone float encoding: enc(a) > enc(b) <=> a > b
__device__ __forceinline__ u32 fenc(float x) {
    u32 b = __float_as_uint(x);
    return (b & 0x80000000u) ? ~b : (b | 0x80000000u);
}
// pack (value, col): larger value wins; tie -> lower col wins
__device__ __forceinline__ u64 fpack(float x, u32 col) {
    return ((u64)fenc(x) << 32) | (u64)(0xFFFFFFFFu - col);
}
#define FIDX(p) (0xFFFFFFFFu - (u32)(p))

// ---------------- normalization + bf16 hi + self-dot ----------------
__global__ void k_normalize(const float* __restrict__ z, const float* __restrict__ sup) {
    int gw = (blockIdx.x * blockDim.x + threadIdx.x) >> 5;
    int lane = threadIdx.x & 31;
    if (gw >= NB + NS) return;
    const float* src;
    float* dst;
    __nv_bfloat16* eh;
    float* selfdot;
    bool isA = gw < NB;
    int r = isA ? gw : gw - NB;
    if (isA) { src = z + (size_t)r * ND; dst = g_zn + (size_t)r * ND; eh = g_Ah + (size_t)r * ND; selfdot = g_XX + r; }
    else     { src = sup + (size_t)r * ND; dst = g_sn + (size_t)r * ND; eh = g_Bh + (size_t)r * ND; selfdot = g_YY + r; }
    float v[16];
    float ss = 0.f;
#pragma unroll
    for (int i = 0; i < 16; i++) {
        float x = src[lane + 32 * i];
        v[i] = x;
        ss += x * x;
    }
#pragma unroll
    for (int o = 16; o; o >>= 1) ss += __shfl_xor_sync(0xffffffffu, ss, o);
    float inv = 1.f / fmaxf(sqrtf(ss), EPS);
    float nn = 0.f;
#pragma unroll
    for (int i = 0; i < 16; i++) {
        float x = v[i] * inv;
        int idx = lane + 32 * i;
        dst[idx] = x;
        eh[idx] = __float2bfloat16(x);
        nn += x * x;
    }
#pragma unroll
    for (int o = 16; o; o >>= 1) nn += __shfl_xor_sync(0xffffffffu, nn, o);
    if (lane == 0) *selfdot = nn;
}

// ---------------- label argmax per support ----------------
__global__ void k_labcls(const float* __restrict__ labels) {
    int n = blockIdx.x * blockDim.x + threadIdx.x;
    if (n >= NS) return;
    const float* r = labels + n * NC;
    float m = r[0]; int mi = 0;
#pragma unroll
    for (int c = 1; c < NC; c++) { float x = r[c]; if (x > m) { m = x; mi = c; } }
    g_labcls[n] = mi;
}

// ---------------- label column sums ----------------
__global__ void k_colsum(const float* __restrict__ labels) {
    __shared__ float sh[256];
    int c = blockIdx.x, tid = threadIdx.x;
    float s = 0.f;
    for (int n = tid; n < NS; n += 256) s += labels[n * NC + c];
    sh[tid] = s;
    __syncthreads();
    for (int st = 128; st; st >>= 1) {
        if (tid < st) sh[tid] += sh[tid + st];
        __syncthreads();
    }
    if (tid == 0) g_cnt[c] = sh[0];
}

// ---------------- centroid partials (atomic-free) ----------------
__global__ void k_cent_part(const float* __restrict__ sup) {
    __shared__ float sp[NC * ND];
    int tid = threadIdx.x;
    for (int i = tid; i < NC * ND; i += 512) sp[i] = 0.f;
    __syncthreads();
    int n0 = blockIdx.x * 32;
    for (int n = 0; n < 32; n++) {
        int c = g_labcls[n0 + n];
        sp[c * ND + tid] += sup[(size_t)(n0 + n) * ND + tid];
    }
    __syncthreads();
    float* dst = g_part + (size_t)blockIdx.x * NC * ND;
    for (int i = tid; i < NC * ND; i += 512) dst[i] = sp[i];
}

__global__ void k_cent_reduce() {
    int i = blockIdx.x * blockDim.x + threadIdx.x;
    if (i >= NC * ND) return;
    float s = 0.f;
    for (int b = 0; b < NPART; b++) s += g_part[(size_t)b * NC * ND + i];
    int c = i / ND;
    g_cent[i] = s / (g_cnt[c] + EPS);
}

__global__ void k_cent_norm() {
    int w = threadIdx.x >> 5, lane = threadIdx.x & 31;
    if (w >= NC) return;
    float v[16];
    float ss = 0.f;
#pragma unroll
    for (int i = 0; i < 16; i++) {
        float x = g_cent[w * ND + lane + 32 * i];
        v[i] = x; ss += x * x;
    }
#pragma unroll
    for (int o = 16; o; o >>= 1) ss += __shfl_xor_sync(0xffffffffu, ss, o);
    float inv = 1.f / fmaxf(sqrtf(ss), EPS);
#pragma unroll
    for (int i = 0; i < 16; i++) g_centn[w * ND + lane + 32 * i] = v[i] * inv;
}

// ---------------- temp_labels: argmax class + softmax per support ----------------
__global__ void k_templabels() {
    __shared__ float sc[NC * ND];
    int tid = threadIdx.x;
    for (int i = tid; i < NC * ND; i += 256) sc[i] = g_centn[i];
    __syncthreads();
    int w = tid >> 5, lane = tid & 31;
    int row = blockIdx.x * 8 + w;
    float acc[NC];
#pragma unroll
    for (int c = 0; c < NC; c++) acc[c] = 0.f;
    const float* sr = g_sn + (size_t)row * ND;
#pragma unroll 4
    for (int i = 0; i < 16; i++) {
        float x = sr[lane + 32 * i];
#pragma unroll
        for (int c = 0; c < NC; c++) acc[c] += x * sc[c * ND + lane + 32 * i];
    }
#pragma unroll
    for (int c = 0; c < NC; c++) {
#pragma unroll
        for (int o = 16; o; o >>= 1) acc[c] += __shfl_xor_sync(0xffffffffu, acc[c], o);
    }
    if (lane == 0) {
        float t[NC];
        float m = -1e30f; int mi = 0;
#pragma unroll
        for (int c = 0; c < NC; c++) {
            t[c] = TAU * acc[c];
            if (t[c] > m) { m = t[c]; mi = c; }
        }
        float s = 0.f;
#pragma unroll
        for (int c = 0; c < NC; c++) { t[c] = expf(t[c] - m); s += t[c]; }
#pragma unroll
        for (int c = 0; c < NC; c++) g_soft[row * NC + c] = t[c] / s;
        g_predcls[row] = mi;
    }
}

// ---------- HMMA GEMM + fused per-tile top-8 candidate extraction ----------
__device__ __forceinline__ void g_load_stage(uint32_t sb, int buf, int k0,
                                             int brow, int bcol, int tid) {
    uint32_t abase = sb + buf * GSTAGE;
    uint32_t bbase = abase + 16384;
#pragma unroll
    for (int i = 0; i < 4; i++) {
        int u = tid + 256 * i;
        int r = u >> 3, sg = u & 7;
        cp16(abase + swz(r * 128 + sg * 16),
             g_Ah + (size_t)(brow + r) * ND + k0 + sg * 8);
    }
#pragma unroll
    for (int i = 0; i < 4; i++) {
        int u = tid + 256 * i;
        int r = u >> 3, sg = u & 7;
        cp16(bbase + swz(r * 128 + sg * 16),
             g_Bh + (size_t)(bcol + r) * ND + k0 + sg * 8);
    }
}

#define TSTR 132   // smem tile row stride (floats)

__global__ __launch_bounds__(256, 2) void k_gemm_mma() {
    extern __shared__ __align__(1024) char smem[];
    uint32_t sb = smem_u32(smem);
    const int tid = threadIdx.x;
    const int brow = blockIdx.y * 128;
    const int bcol = blockIdx.x * 128;
    const int w = tid >> 5, lane = tid & 31;
    const int wm = (w >> 2) * 64;   // 2 warps in m
    const int wn = (w & 3) * 32;    // 4 warps in n

    float acc[4][4][4];
#pragma unroll
    for (int a = 0; a < 4; a++)
#pragma unroll
        for (int b = 0; b < 4; b++)
#pragma unroll
            for (int c = 0; c < 4; c++) acc[a][b][c] = 0.f;

    g_load_stage(sb, 0, 0, brow, bcol, tid);
    CP_COMMIT();
    g_load_stage(sb, 1, 64, brow, bcol, tid);
    CP_COMMIT();

#pragma unroll 1
    for (int it = 0; it < GITERS; it++) {
        asm volatile("cp.async.wait_group 1;" ::: "memory");
        __syncthreads();
        if (it + 2 < GITERS)
            g_load_stage(sb, (it + 2) % 3, (it + 2) * 64, brow, bcol, tid);
        CP_COMMIT();

        uint32_t As = sb + (it % 3) * GSTAGE;
        uint32_t Bs = As + 16384;
#pragma unroll
        for (int ks = 0; ks < 4; ks++) {
            uint32_t af[4][4], bf[4][2];
#pragma unroll
            for (int mt = 0; mt < 4; mt++) {
                uint32_t row = wm + mt * 16 + (lane & 15);
                uint32_t cb = ks * 32 + ((lane >> 4) << 4);
                ldsm4(af[mt], As + swz(row * 128 + cb));
            }
#pragma unroll
            for (int nt = 0; nt < 4; nt++) {
                uint32_t row = wn + nt * 8 + (lane & 7);
                uint32_t cb = ks * 32 + (((lane >> 3) & 1) << 4);
                ldsm2(bf[nt], Bs + swz(row * 128 + cb));
            }
#pragma unroll
            for (int mt = 0; mt < 4; mt++)
#pragma unroll
                for (int nt = 0; nt < 4; nt++)
                    mma16816(acc[mt][nt], af[mt], bf[nt]);
        }
    }

    // ---- fused epilogue: per-row top-8 within this 128-col tile ----
    asm volatile("cp.async.wait_group 0;" ::: "memory");
    __syncthreads();  // all ldsm reads done; stage buffers reusable
    float* stile = (float*)smem;  // 128 x TSTR fp32 (67.6 KB of the 96 KB)
#pragma unroll
    for (int mt = 0; mt < 4; mt++) {
        int r0 = wm + mt * 16 + (lane >> 2);
#pragma unroll
        for (int nt = 0; nt < 4; nt++) {
            int c0 = wn + nt * 8 + (lane & 3) * 2;
            stile[r0 * TSTR + c0] = acc[mt][nt][0];
            stile[r0 * TSTR + c0 + 1] = acc[mt][nt][1];
            stile[(r0 + 8) * TSTR + c0] = acc[mt][nt][2];
            stile[(r0 + 8) * TSTR + c0 + 1] = acc[mt][nt][3];
        }
    }
    __syncthreads();

    // warp w handles rows w*16 .. w*16+15
#pragma unroll 1
    for (int i = 0; i < 16; i++) {
        int row = w * 16 + i;
        float4 vv = *(const float4*)&stile[row * TSTR + lane * 4];
        u32 cbase = (u32)(bcol + lane * 4);
        u64 l0 = fpack(vv.x, cbase);
        u64 l1 = fpack(vv.y, cbase + 1);
        u64 l2 = fpack(vv.z, cbase + 2);
        u64 l3 = fpack(vv.w, cbase + 3);
        // sort 4 desc
        u64 t;
        if (l0 < l1) { t = l0; l0 = l1; l1 = t; }
        if (l2 < l3) { t = l2; l2 = l3; l3 = t; }
        if (l0 < l2) { t = l0; l0 = l2; l2 = t; }
        if (l1 < l3) { t = l1; l1 = l3; l3 = t; }
        if (l1 < l2) { t = l1; l1 = l2; l2 = t; }
        u64* dst = g_cand + ((size_t)(brow + row) * NTILE + blockIdx.x) * KTOP;
#pragma unroll
        for (int r = 0; r < KTOP; r++) {
            u64 m = l0;
#pragma unroll
            for (int o = 16; o; o >>= 1) {
                u64 p = __shfl_xor_sync(0xffffffffu, m, o);
                if (p > m) m = p;
            }
            if (l0 == m) { l0 = l1; l1 = l2; l2 = l3; l3 = 0; }
            if (lane == 0) dst[r] = m;
        }
    }
}

// ------- per-row: merge 1024 candidates -> top-16 -> exact rescore -> top-8 ------
__global__ void k_select(float* __restrict__ out) {
    __shared__ float zrow[ND];
    __shared__ u64 sh_w[8];
    __shared__ u64 sh_win;
    __shared__ u64 wlist[KCAND];
    __shared__ int widx[KCAND];
    __shared__ float cdist[KCAND];
    __shared__ int sel[KTOP];
    __shared__ float st[NC], so[NC], ssum[2];
    const int row = blockIdx.x;
    const int tid = threadIdx.x;
    const int w = tid >> 5, lane = tid & 31;

    zrow[tid] = g_zn[(size_t)row * ND + tid];
    zrow[tid + 256] = g_zn[(size_t)row * ND + tid + 256];

    const u64* cand = g_cand + (size_t)row * (NTILE * KTOP);
    u64 l0 = cand[tid], l1 = cand[tid + 256], l2 = cand[tid + 512], l3 = cand[tid + 768];
    u64 t;
    if (l0 < l1) { t = l0; l0 = l1; l1 = t; }
    if (l2 < l3) { t = l2; l2 = l3; l3 = t; }
    if (l0 < l2) { t = l0; l0 = l2; l2 = t; }
    if (l1 < l3) { t = l1; l1 = l3; l3 = t; }
    if (l1 < l2) { t = l1; l1 = l2; l2 = t; }

#pragma unroll 1
    for (int r = 0; r < KCAND; r++) {
        u64 m = l0;
#pragma unroll
        for (int o = 16; o; o >>= 1) {
            u64 p = __shfl_xor_sync(0xffffffffu, m, o);
            if (p > m) m = p;
        }
        if (lane == 0) sh_w[w] = m;
        __syncthreads();
        if (tid == 0) {
            u64 b = sh_w[0];
#pragma unroll
            for (int j = 1; j < 8; j++) if (sh_w[j] > b) b = sh_w[j];
            sh_win = b;
            wlist[r] = b;
        }
        __syncthreads();
        u64 win = sh_win;
        if (l0 == win) { l0 = l1; l1 = l2; l2 = l3; l3 = 0; }
        __syncthreads();
    }

    if (tid < KCAND) widx[tid] = (int)FIDX(wlist[tid]);
    __syncthreads();

    // exact fp32 rescore: dist = XX + YY - 2*dot
    {
        float XXr = g_XX[row];
        for (int candi = w; candi < KCAND; candi += 8) {
            int n = widx[candi];
            const float* sr = g_sn + (size_t)n * ND;
            float d = 0.f;
#pragma unroll 4
            for (int i = 0; i < 16; i++) d += zrow[lane + 32 * i] * sr[lane + 32 * i];
#pragma unroll
            for (int o = 16; o; o >>= 1) d += __shfl_xor_sync(0xffffffffu, d, o);
            if (lane == 0) cdist[candi] = XXr + g_YY[n] - 2.f * d;
        }
    }
    __syncthreads();

    // select 8 smallest dist (tie -> lower support index)
    if (tid == 0) {
        unsigned used = 0;
#pragma unroll
        for (int k = 0; k < KTOP; k++) {
            float bd = 1e30f; int bi = -1, bn = 1 << 30;
#pragma unroll
            for (int c = 0; c < KCAND; c++) {
                if (used & (1u << c)) continue;
                float dc = cdist[c]; int nc_ = widx[c];
                if (dc < bd || (dc == bd && nc_ < bn)) { bd = dc; bi = c; bn = nc_; }
            }
            used |= 1u << bi;
            sel[k] = bn;
        }
    }
    __syncthreads();

    if (tid < NC) {
        float o = 0.f, tg = 0.f;
#pragma unroll
        for (int k = 0; k < KTOP; k++) {
            int n = sel[k];
            o += g_soft[n * NC + tid];
            tg += (g_predcls[n] == tid) ? 1.f : 0.f;
        }
        st[tid] = tg; so[tid] = o;
    }
    __syncthreads();
    if (tid == 0) {
        float ts = 0.f, os = 0.f;
#pragma unroll
        for (int c = 0; c < NC; c++) { ts += st[c]; os += so[c]; }
        ssum[0] = ts; ssum[1] = os;
    }
    __syncthreads();
    if (tid < NC) {
        out[(size_t)NB * NC + row * NC + tid] = st[tid] / (ssum[0] + EPS);
        out[(size_t)2 * NB * NC + row * NC + tid] = so[tid] / (ssum[1] + EPS);
    }
}

// ---------------- logits = TAU * zn @ centn^T ----------------
__global__ void k_logits(float* __restrict__ out) {
    __shared__ float sc[NC * ND];
    int tid = threadIdx.x;
    for (int i = tid; i < NC * ND; i += 256) sc[i] = g_centn[i];
    __syncthreads();
    int w = tid >> 5, lane = tid & 31;
    int row = blockIdx.x * 8 + w;
    float acc[NC];
#pragma unroll
    for (int c = 0; c < NC; c++) acc[c] = 0.f;
    const float* zr = g_zn + (size_t)row * ND;
#pragma unroll 4
    for (int i = 0; i < 16; i++) {
        float x = zr[lane + 32 * i];
#pragma unroll
        for (int c = 0; c < NC; c++) acc[c] += x * sc[c * ND + lane + 32 * i];
    }
#pragma unroll
    for (int c = 0; c < NC; c++) {
#pragma unroll
        for (int o = 16; o; o >>= 1) acc[c] += __shfl_xor_sync(0xffffffffu, acc[c], o);
    }
    if (lane == 0) {
#pragma unroll
        for (int c = 0; c < NC; c++) out[row * NC + c] = TAU * acc[c];
    }
}

// ---------------- launch ----------------
extern "C" void kernel_launch(void* const* d_in, const int* in_sizes, int n_in,
                              void* d_out, int out_size) {
    const float* z = (const float*)d_in[0];
    const float* supports = (const float*)d_in[1];
    const float* labels = (const float*)d_in[2];
    float* out = (float*)d_out;

    cudaFuncSetAttribute(k_gemm_mma, cudaFuncAttributeMaxDynamicSharedMemorySize,
                         GEMM_SMEM);

    k_normalize<<<(NB + NS) / 8, 256>>>(z, supports);
    k_labcls<<<NS / 256, 256>>>(labels);
    k_colsum<<<NC, 256>>>(labels);
    k_cent_part<<<NPART, 512>>>(supports);
    k_cent_reduce<<<(NC * ND + 255) / 256, 256>>>();
    k_cent_norm<<<1, NC * 32>>>();
    k_templabels<<<NS / 8, 256>>>();
    dim3 gg(NS / 128, NB / 128);
    k_gemm_mma<<<gg, 256, GEMM_SMEM>>>();
    k_select<<<NB, 256>>>(out);
    k_logits<<<NB / 8, 256>>>(out);
}

// round 6
// speedup vs baseline: 3.3163x; 1.2283x over previous
#include <cuda_runtime.h>
#include <cuda_bf16.h>
#include <math.h>
#include <stdint.h>

typedef unsigned long long u64;
typedef unsigned int u32;

// Problem constants
#define NB 2048     // queries
#define NS 16384    // supports
#define ND 512      // dim
#define NC 17       // classes
#define KTOP 8
#define KCAND 16    // candidates rescored exactly
#define TAU 10.0f
#define EPS 1e-12f

#define GITERS 8          // ND / 64
#define ASTAGE 16384      // 128 rows x 128B
#define BSTAGE 32768      // 256 rows x 128B
#define GSTAGE (ASTAGE + BSTAGE)
#define GEMM_SMEM (2 * GSTAGE)   // 96 KB
#define NT64 256          // NS / 64 column tiles per row
#define NPART 512         // centroid partial chunks

// ---------------- scratch (device globals; no runtime alloc) ----------------
__device__ float g_zn[NB * ND];            // normalized z (fp32, exact)
__device__ float g_sn[NS * ND];            // normalized supports (fp32, exact)
__device__ float g_XX[NB];                 // sum(zn^2) per row
__device__ float g_YY[NS];                 // sum(sn^2) per support
__device__ float g_cent[NC * ND];
__device__ float g_centn[NC * ND];
__device__ float g_cnt[NC];
__device__ int   g_labcls[NS];
__device__ int   g_predcls[NS];
__device__ float g_soft[NS * NC];
__device__ float g_part[NPART * NC * ND];
__device__ __align__(16) __nv_bfloat16 g_Ah[NB * ND];   // bf16(zn)
__device__ __align__(16) __nv_bfloat16 g_Bh[NS * ND];   // bf16(sn)
__device__ u64 g_cand[(size_t)NB * NT64 * 4];           // per-64col-tile top-4 (16 MB)

// ---------------- PTX helpers ----------------
__device__ __forceinline__ uint32_t smem_u32(const void* p) {
    uint32_t a;
    asm("{ .reg .u64 t; cvta.to.shared.u64 t, %1; cvt.u32.u64 %0, t; }" : "=r"(a) : "l"(p));
    return a;
}
__device__ __forceinline__ void cp16(uint32_t saddr, const void* g) {
    asm volatile("cp.async.cg.shared.global [%0], [%1], 16;" :: "r"(saddr), "l"(g));
}
#define CP_COMMIT() asm volatile("cp.async.commit_group;" ::: "memory")

__device__ __forceinline__ void ldsm4(uint32_t* r, uint32_t addr) {
    asm volatile("ldmatrix.sync.aligned.m8n8.x4.shared.b16 {%0,%1,%2,%3}, [%4];"
        : "=r"(r[0]), "=r"(r[1]), "=r"(r[2]), "=r"(r[3]) : "r"(addr));
}
__device__ __forceinline__ void mma16816(float* d, const uint32_t* a, const uint32_t* b) {
    asm volatile(
        "mma.sync.aligned.m16n8k16.row.col.f32.bf16.bf16.f32 "
        "{%0,%1,%2,%3}, {%4,%5,%6,%7}, {%8,%9}, {%0,%1,%2,%3};"
        : "+f"(d[0]), "+f"(d[1]), "+f"(d[2]), "+f"(d[3])
        : "r"(a[0]), "r"(a[1]), "r"(a[2]), "r"(a[3]), "r"(b[0]), "r"(b[1]));
}
__device__ __forceinline__ uint32_t swz(uint32_t o) { return o ^ ((o >> 3) & 0x70); }

// monotone float encoding: enc(a) > enc(b) <=> a > b
__device__ __forceinline__ u32 fenc(float x) {
    u32 b = __float_as_uint(x);
    return (b & 0x80000000u) ? ~b : (b | 0x80000000u);
}
__device__ __forceinline__ u64 fpack(float x, u32 col) {
    return ((u64)fenc(x) << 32) | (u64)(0xFFFFFFFFu - col);
}
#define FIDX(p) (0xFFFFFFFFu - (u32)(p))

#define CE(a, b) do { if ((a) < (b)) { u64 _t = (a); (a) = (b); (b) = _t; } } while (0)

// ---------------- normalization + bf16 hi + self-dot ----------------
__global__ void k_normalize(const float* __restrict__ z, const float* __restrict__ sup) {
    int gw = (blockIdx.x * blockDim.x + threadIdx.x) >> 5;
    int lane = threadIdx.x & 31;
    if (gw >= NB + NS) return;
    const float* src;
    float* dst;
    __nv_bfloat16* eh;
    float* selfdot;
    bool isA = gw < NB;
    int r = isA ? gw : gw - NB;
    if (isA) { src = z + (size_t)r * ND; dst = g_zn + (size_t)r * ND; eh = g_Ah + (size_t)r * ND; selfdot = g_XX + r; }
    else     { src = sup + (size_t)r * ND; dst = g_sn + (size_t)r * ND; eh = g_Bh + (size_t)r * ND; selfdot = g_YY + r; }
    float v[16];
    float ss = 0.f;
#pragma unroll
    for (int i = 0; i < 16; i++) {
        float x = src[lane + 32 * i];
        v[i] = x;
        ss += x * x;
    }
#pragma unroll
    for (int o = 16; o; o >>= 1) ss += __shfl_xor_sync(0xffffffffu, ss, o);
    float inv = 1.f / fmaxf(sqrtf(ss), EPS);
    float nn = 0.f;
#pragma unroll
    for (int i = 0; i < 16; i++) {
        float x = v[i] * inv;
        int idx = lane + 32 * i;
        dst[idx] = x;
        eh[idx] = __float2bfloat16(x);
        nn += x * x;
    }
#pragma unroll
    for (int o = 16; o; o >>= 1) nn += __shfl_xor_sync(0xffffffffu, nn, o);
    if (lane == 0) *selfdot = nn;
}

// ---------------- label argmax per support ----------------
__global__ void k_labcls(const float* __restrict__ labels) {
    int n = blockIdx.x * blockDim.x + threadIdx.x;
    if (n >= NS) return;
    const float* r = labels + n * NC;
    float m = r[0]; int mi = 0;
#pragma unroll
    for (int c = 1; c < NC; c++) { float x = r[c]; if (x > m) { m = x; mi = c; } }
    g_labcls[n] = mi;
}

// ---------------- label column sums ----------------
__global__ void k_colsum(const float* __restrict__ labels) {
    __shared__ float sh[256];
    int c = blockIdx.x, tid = threadIdx.x;
    float s = 0.f;
    for (int n = tid; n < NS; n += 256) s += labels[n * NC + c];
    sh[tid] = s;
    __syncthreads();
    for (int st = 128; st; st >>= 1) {
        if (tid < st) sh[tid] += sh[tid + st];
        __syncthreads();
    }
    if (tid == 0) g_cnt[c] = sh[0];
}

// ---------------- centroid partials (atomic-free) ----------------
__global__ void k_cent_part(const float* __restrict__ sup) {
    __shared__ float sp[NC * ND];
    int tid = threadIdx.x;
    for (int i = tid; i < NC * ND; i += 512) sp[i] = 0.f;
    __syncthreads();
    int n0 = blockIdx.x * 32;
    for (int n = 0; n < 32; n++) {
        int c = g_labcls[n0 + n];
        sp[c * ND + tid] += sup[(size_t)(n0 + n) * ND + tid];
    }
    __syncthreads();
    float* dst = g_part + (size_t)blockIdx.x * NC * ND;
    for (int i = tid; i < NC * ND; i += 512) dst[i] = sp[i];
}

__global__ void k_cent_reduce() {
    int i = blockIdx.x * blockDim.x + threadIdx.x;
    if (i >= NC * ND) return;
    float s = 0.f;
    for (int b = 0; b < NPART; b++) s += g_part[(size_t)b * NC * ND + i];
    int c = i / ND;
    g_cent[i] = s / (g_cnt[c] + EPS);
}

__global__ void k_cent_norm() {
    int w = threadIdx.x >> 5, lane = threadIdx.x & 31;
    if (w >= NC) return;
    float v[16];
    float ss = 0.f;
#pragma unroll
    for (int i = 0; i < 16; i++) {
        float x = g_cent[w * ND + lane + 32 * i];
        v[i] = x; ss += x * x;
    }
#pragma unroll
    for (int o = 16; o; o >>= 1) ss += __shfl_xor_sync(0xffffffffu, ss, o);
    float inv = 1.f / fmaxf(sqrtf(ss), EPS);
#pragma unroll
    for (int i = 0; i < 16; i++) g_centn[w * ND + lane + 32 * i] = v[i] * inv;
}

// ---------------- temp_labels: argmax class + softmax per support ----------------
__global__ void k_templabels() {
    __shared__ float sc[NC * ND];
    int tid = threadIdx.x;
    for (int i = tid; i < NC * ND; i += 256) sc[i] = g_centn[i];
    __syncthreads();
    int w = tid >> 5, lane = tid & 31;
    int row = blockIdx.x * 8 + w;
    float acc[NC];
#pragma unroll
    for (int c = 0; c < NC; c++) acc[c] = 0.f;
    const float* sr = g_sn + (size_t)row * ND;
#pragma unroll 4
    for (int i = 0; i < 16; i++) {
        float x = sr[lane + 32 * i];
#pragma unroll
        for (int c = 0; c < NC; c++) acc[c] += x * sc[c * ND + lane + 32 * i];
    }
#pragma unroll
    for (int c = 0; c < NC; c++) {
#pragma unroll
        for (int o = 16; o; o >>= 1) acc[c] += __shfl_xor_sync(0xffffffffu, acc[c], o);
    }
    if (lane == 0) {
        float t[NC];
        float m = -1e30f; int mi = 0;
#pragma unroll
        for (int c = 0; c < NC; c++) {
            t[c] = TAU * acc[c];
            if (t[c] > m) { m = t[c]; mi = c; }
        }
        float s = 0.f;
#pragma unroll
        for (int c = 0; c < NC; c++) { t[c] = expf(t[c] - m); s += t[c]; }
#pragma unroll
        for (int c = 0; c < NC; c++) g_soft[row * NC + c] = t[c] / s;
        g_predcls[row] = mi;
    }
}

// ---------- HMMA GEMM 128x256 tile + register-resident per-tile top-4 ----------
__device__ __forceinline__ void g_load_stage(uint32_t sb, int buf, int k0,
                                             int brow, int bcol, int tid) {
    uint32_t abase = sb + buf * GSTAGE;
    uint32_t bbase = abase + ASTAGE;
#pragma unroll
    for (int i = 0; i < 4; i++) {
        int u = tid + 256 * i;
        int r = u >> 3, sg = u & 7;
        cp16(abase + swz(r * 128 + sg * 16),
             g_Ah + (size_t)(brow + r) * ND + k0 + sg * 8);
    }
#pragma unroll
    for (int i = 0; i < 8; i++) {
        int u = tid + 256 * i;
        int r = u >> 3, sg = u & 7;
        cp16(bbase + swz(r * 128 + sg * 16),
             g_Bh + (size_t)(bcol + r) * ND + k0 + sg * 8);
    }
}

__global__ __launch_bounds__(256, 1) void k_gemm_mma() {
    extern __shared__ __align__(1024) char smem[];
    uint32_t sb = smem_u32(smem);
    const int tid = threadIdx.x;
    const int brow = blockIdx.y * 128;
    const int bcol = blockIdx.x * 256;
    const int w = tid >> 5, lane = tid & 31;
    const int wm = (w >> 2) * 64;   // 2 warps in m
    const int wn = (w & 3) * 64;    // 4 warps in n

    float acc[4][8][4];
#pragma unroll
    for (int a = 0; a < 4; a++)
#pragma unroll
        for (int b = 0; b < 8; b++)
#pragma unroll
            for (int c = 0; c < 4; c++) acc[a][b][c] = 0.f;

    g_load_stage(sb, 0, 0, brow, bcol, tid);
    CP_COMMIT();
    g_load_stage(sb, 1, 64, brow, bcol, tid);
    CP_COMMIT();

    // A frag address: row = wm + mt*16 + (lane&15), col byte = cb + ((lane>>4)<<4)
    const u32 a_row = wm + (lane & 15);
    const u32 a_cbo = (lane >> 4) << 4;
    // B frag (paired n8 tiles): row = wn + ntp*16 + (lane&7) + ((lane>>4)<<3)
    const u32 b_row = wn + (lane & 7) + ((lane >> 4) << 3);
    const u32 b_cbo = ((lane >> 3) & 1) << 4;

#pragma unroll 1
    for (int it = 0; it < GITERS; it++) {
        asm volatile("cp.async.wait_group 1;" ::: "memory");
        __syncthreads();

        uint32_t As = sb + (it & 1) * GSTAGE;
        uint32_t Bs = As + ASTAGE;
#pragma unroll
        for (int ks = 0; ks < 4; ks++) {
            u32 cb = ks * 32;
            uint32_t af[4][4], bf[4][4];
#pragma unroll
            for (int mt = 0; mt < 4; mt++)
                ldsm4(af[mt], As + swz((a_row + mt * 16) * 128 + cb + a_cbo));
#pragma unroll
            for (int ntp = 0; ntp < 4; ntp++)
                ldsm4(bf[ntp], Bs + swz((b_row + ntp * 16) * 128 + cb + b_cbo));
#pragma unroll
            for (int mt = 0; mt < 4; mt++)
#pragma unroll
                for (int nt = 0; nt < 8; nt++)
                    mma16816(acc[mt][nt], af[mt], &bf[nt >> 1][(nt & 1) * 2]);
        }
        __syncthreads();
        if (it + 2 < GITERS)
            g_load_stage(sb, it & 1, (it + 2) * 64, brow, bcol, tid);
        CP_COMMIT();
    }

    // ---- register-resident epilogue: per-row top-4 within this 64-col warp tile ----
    const int g = lane >> 2;        // row group 0..7
    const int qt = lane & 3;        // quad thread
    const int tile64 = blockIdx.x * 4 + (w & 3);
    const u32 colbase = (u32)(bcol + wn + qt * 2);
#pragma unroll
    for (int mt = 0; mt < 4; mt++) {
#pragma unroll
        for (int h = 0; h < 2; h++) {
            int row = brow + wm + mt * 16 + h * 8 + g;
            u64 s0 = 0, s1 = 0, s2 = 0, s3 = 0;
#pragma unroll
            for (int nt = 0; nt < 8; nt++) {
#pragma unroll
                for (int e = 0; e < 2; e++) {
                    u64 p = fpack(acc[mt][nt][h * 2 + e], colbase + nt * 8 + e);
                    if (p > s3) {
                        s3 = p;
                        CE(s2, s3); CE(s1, s2); CE(s0, s1);
                    }
                }
            }
            // merge sorted-4 lists across the quad (xor 1, then xor 2)
#pragma unroll
            for (int d = 1; d <= 2; d <<= 1) {
                u64 t0 = __shfl_xor_sync(0xffffffffu, s0, d);
                u64 t1 = __shfl_xor_sync(0xffffffffu, s1, d);
                u64 t2 = __shfl_xor_sync(0xffffffffu, s2, d);
                u64 t3 = __shfl_xor_sync(0xffffffffu, s3, d);
                s0 = s0 > t3 ? s0 : t3;
                s1 = s1 > t2 ? s1 : t2;
                s2 = s2 > t1 ? s2 : t1;
                s3 = s3 > t0 ? s3 : t0;
                CE(s0, s2); CE(s1, s3); CE(s0, s1); CE(s2, s3);
            }
            if (qt == 0) {
                u64* dst = g_cand + ((size_t)row * NT64 + tile64) * 4;
                dst[0] = s0; dst[1] = s1; dst[2] = s2; dst[3] = s3;
            }
        }
    }
}

// ------- per-row: merge 1024 candidates -> top-16 -> exact rescore -> top-8 ------
__global__ void k_select(float* __restrict__ out) {
    __shared__ float zrow[ND];
    __shared__ u64 sh_w[8];
    __shared__ u64 sh_win;
    __shared__ u64 wlist[KCAND];
    __shared__ int widx[KCAND];
    __shared__ float cdist[KCAND];
    __shared__ int sel[KTOP];
    __shared__ float st[NC], so[NC], ssum[2];
    const int row = blockIdx.x;
    const int tid = threadIdx.x;
    const int w = tid >> 5, lane = tid & 31;

    zrow[tid] = g_zn[(size_t)row * ND + tid];
    zrow[tid + 256] = g_zn[(size_t)row * ND + tid + 256];

    const u64* cand = g_cand + (size_t)row * (NT64 * 4);
    u64 l0 = cand[tid], l1 = cand[tid + 256], l2 = cand[tid + 512], l3 = cand[tid + 768];
    u64 t;
    CE(l0, l1); CE(l2, l3); CE(l0, l2); CE(l1, l3); CE(l1, l2);
    (void)t;

#pragma unroll 1
    for (int r = 0; r < KCAND; r++) {
        u64 m = l0;
#pragma unroll
        for (int o = 16; o; o >>= 1) {
            u64 p = __shfl_xor_sync(0xffffffffu, m, o);
            if (p > m) m = p;
        }
        if (lane == 0) sh_w[w] = m;
        __syncthreads();
        if (tid == 0) {
            u64 b = sh_w[0];
#pragma unroll
            for (int j = 1; j < 8; j++) if (sh_w[j] > b) b = sh_w[j];
            sh_win = b;
            wlist[r] = b;
        }
        __syncthreads();
        u64 win = sh_win;
        if (l0 == win) { l0 = l1; l1 = l2; l2 = l3; l3 = 0; }
        __syncthreads();
    }

    if (tid < KCAND) widx[tid] = (int)FIDX(wlist[tid]);
    __syncthreads();

    // exact fp32 rescore: dist = XX + YY - 2*dot
    {
        float XXr = g_XX[row];
        for (int candi = w; candi < KCAND; candi += 8) {
            int n = widx[candi];
            const float* sr = g_sn + (size_t)n * ND;
            float d = 0.f;
#pragma unroll 4
            for (int i = 0; i < 16; i++) d += zrow[lane + 32 * i] * sr[lane + 32 * i];
#pragma unroll
            for (int o = 16; o; o >>= 1) d += __shfl_xor_sync(0xffffffffu, d, o);
            if (lane == 0) cdist[candi] = XXr + g_YY[n] - 2.f * d;
        }
    }
    __syncthreads();

    // select 8 smallest dist (tie -> lower support index)
    if (tid == 0) {
        unsigned used = 0;
#pragma unroll
        for (int k = 0; k < KTOP; k++) {
            float bd = 1e30f; int bi = -1, bn = 1 << 30;
#pragma unroll
            for (int c = 0; c < KCAND; c++) {
                if (used & (1u << c)) continue;
                float dc = cdist[c]; int nc_ = widx[c];
                if (dc < bd || (dc == bd && nc_ < bn)) { bd = dc; bi = c; bn = nc_; }
            }
            used |= 1u << bi;
            sel[k] = bn;
        }
    }
    __syncthreads();

    if (tid < NC) {
        float o = 0.f, tg = 0.f;
#pragma unroll
        for (int k = 0; k < KTOP; k++) {
            int n = sel[k];
            o += g_soft[n * NC + tid];
            tg += (g_predcls[n] == tid) ? 1.f : 0.f;
        }
        st[tid] = tg; so[tid] = o;
    }
    __syncthreads();
    if (tid == 0) {
        float ts = 0.f, os = 0.f;
#pragma unroll
        for (int c = 0; c < NC; c++) { ts += st[c]; os += so[c]; }
        ssum[0] = ts; ssum[1] = os;
    }
    __syncthreads();
    if (tid < NC) {
        out[(size_t)NB * NC + row * NC + tid] = st[tid] / (ssum[0] + EPS);
        out[(size_t)2 * NB * NC + row * NC + tid] = so[tid] / (ssum[1] + EPS);
    }
}

// ---------------- logits = TAU * zn @ centn^T ----------------
__global__ void k_logits(float* __restrict__ out) {
    __shared__ float sc[NC * ND];
    int tid = threadIdx.x;
    for (int i = tid; i < NC * ND; i += 256) sc[i] = g_centn[i];
    __syncthreads();
    int w = tid >> 5, lane = tid & 31;
    int row = blockIdx.x * 8 + w;
    float acc[NC];
#pragma unroll
    for (int c = 0; c < NC; c++) acc[c] = 0.f;
    const float* zr = g_zn + (size_t)row * ND;
#pragma unroll 4
    for (int i = 0; i < 16; i++) {
        float x = zr[lane + 32 * i];
#pragma unroll
        for (int c = 0; c < NC; c++) acc[c] += x * sc[c * ND + lane + 32 * i];
    }
#pragma unroll
    for (int c = 0; c < NC; c++) {
#pragma unroll
        for (int o = 16; o; o >>= 1) acc[c] += __shfl_xor_sync(0xffffffffu, acc[c], o);
    }
    if (lane == 0) {
#pragma unroll
        for (int c = 0; c < NC; c++) out[row * NC + c] = TAU * acc[c];
    }
}

// ---------------- launch ----------------
extern "C" void kernel_launch(void* const* d_in, const int* in_sizes, int n_in,
                              void* d_out, int out_size) {
    const float* z = (const float*)d_in[0];
    const float* supports = (const float*)d_in[1];
    const float* labels = (const float*)d_in[2];
    float* out = (float*)d_out;

    cudaFuncSetAttribute(k_gemm_mma, cudaFuncAttributeMaxDynamicSharedMemorySize,
                         GEMM_SMEM);

    // NOTE: launch order puts k_gemm_mma in the ncu-profiled slot (was k_cent_part).
    k_normalize<<<(NB + NS) / 8, 256>>>(z, supports);
    k_labcls<<<NS / 256, 256>>>(labels);
    k_colsum<<<NC, 256>>>(labels);
    dim3 gg(NS / 256, NB / 128);
    k_gemm_mma<<<gg, 256, GEMM_SMEM>>>();
    k_cent_part<<<NPART, 512>>>(supports);
    k_cent_reduce<<<(NC * ND + 255) / 256, 256>>>();
    k_cent_norm<<<1, NC * 32>>>();
    k_templabels<<<NS / 8, 256>>>();
    k_select<<<NB, 256>>>(out);
    k_logits<<<NB / 8, 256>>>(out);
}

// round 7
// speedup vs baseline: 3.4411x; 1.0376x over previous
#include <cuda_runtime.h>
#include <cuda_bf16.h>
#include <math.h>
#include <stdint.h>

typedef unsigned long long u64;
typedef unsigned int u32;

// Problem constants
#define NB 2048     // queries
#define NS 16384    // supports
#define ND 512      // dim
#define NC 17       // classes
#define KTOP 8
#define KCAND 16    // candidates rescored exactly
#define TAU 10.0f
#define EPS 1e-12f

#define GITERS 8          // ND / 64
#define ASTAGE 16384      // 128 rows x 128B
#define BSTAGE 32768      // 256 rows x 128B
#define GSTAGE (ASTAGE + BSTAGE)
#define GEMM_SMEM (2 * GSTAGE)   // 96 KB
#define NT64 256          // NS / 64 column tiles per row
#define NPART 512         // centroid partial chunks

// ---------------- scratch (device globals; no runtime alloc) ----------------
__device__ float g_zn[NB * ND];            // normalized z (fp32, exact)
__device__ float g_sn[NS * ND];            // normalized supports (fp32, exact)
__device__ float g_XX[NB];                 // sum(zn^2) per row
__device__ float g_YY[NS];                 // sum(sn^2) per support
__device__ float g_cent[NC * ND];
__device__ float g_centn[NC * ND];
__device__ float g_cnt[NC];
__device__ int   g_labcls[NS];
__device__ int   g_predcls[NS];
__device__ float g_soft[NS * NC];
__device__ float g_part[NPART * NC * ND];
__device__ __align__(16) __nv_bfloat16 g_Ah[NB * ND];   // bf16(zn)
__device__ __align__(16) __nv_bfloat16 g_Bh[NS * ND];   // bf16(sn)
__device__ u64 g_cand[(size_t)NB * NT64 * 4];           // per-64col-tile top-4 (16 MB)

// ---------------- PTX helpers ----------------
__device__ __forceinline__ uint32_t smem_u32(const void* p) {
    uint32_t a;
    asm("{ .reg .u64 t; cvta.to.shared.u64 t, %1; cvt.u32.u64 %0, t; }" : "=r"(a) : "l"(p));
    return a;
}
__device__ __forceinline__ void cp16(uint32_t saddr, const void* g) {
    asm volatile("cp.async.cg.shared.global [%0], [%1], 16;" :: "r"(saddr), "l"(g));
}
#define CP_COMMIT() asm volatile("cp.async.commit_group;" ::: "memory")

__device__ __forceinline__ void ldsm4(uint32_t* r, uint32_t addr) {
    asm volatile("ldmatrix.sync.aligned.m8n8.x4.shared.b16 {%0,%1,%2,%3}, [%4];"
        : "=r"(r[0]), "=r"(r[1]), "=r"(r[2]), "=r"(r[3]) : "r"(addr));
}
__device__ __forceinline__ void mma16816(float* d, const uint32_t* a, const uint32_t* b) {
    asm volatile(
        "mma.sync.aligned.m16n8k16.row.col.f32.bf16.bf16.f32 "
        "{%0,%1,%2,%3}, {%4,%5,%6,%7}, {%8,%9}, {%0,%1,%2,%3};"
        : "+f"(d[0]), "+f"(d[1]), "+f"(d[2]), "+f"(d[3])
        : "r"(a[0]), "r"(a[1]), "r"(a[2]), "r"(a[3]), "r"(b[0]), "r"(b[1]));
}
__device__ __forceinline__ uint32_t swz(uint32_t o) { return o ^ ((o >> 3) & 0x70); }

// monotone float encoding: enc(a) > enc(b) <=> a > b
__device__ __forceinline__ u32 fenc(float x) {
    u32 b = __float_as_uint(x);
    return (b & 0x80000000u) ? ~b : (b | 0x80000000u);
}
__device__ __forceinline__ u64 fpack(float x, u32 col) {
    return ((u64)fenc(x) << 32) | (u64)(0xFFFFFFFFu - col);
}
#define FIDX(p) (0xFFFFFFFFu - (u32)(p))

#define CE(a, b) do { if ((a) < (b)) { u64 _t = (a); (a) = (b); (b) = _t; } } while (0)

// ---------------- normalization + bf16 hi + self-dot ----------------
__global__ void k_normalize(const float* __restrict__ z, const float* __restrict__ sup) {
    int gw = (blockIdx.x * blockDim.x + threadIdx.x) >> 5;
    int lane = threadIdx.x & 31;
    if (gw >= NB + NS) return;
    const float* src;
    float* dst;
    __nv_bfloat16* eh;
    float* selfdot;
    bool isA = gw < NB;
    int r = isA ? gw : gw - NB;
    if (isA) { src = z + (size_t)r * ND; dst = g_zn + (size_t)r * ND; eh = g_Ah + (size_t)r * ND; selfdot = g_XX + r; }
    else     { src = sup + (size_t)r * ND; dst = g_sn + (size_t)r * ND; eh = g_Bh + (size_t)r * ND; selfdot = g_YY + r; }
    float v[16];
    float ss = 0.f;
#pragma unroll
    for (int i = 0; i < 16; i++) {
        float x = src[lane + 32 * i];
        v[i] = x;
        ss += x * x;
    }
#pragma unroll
    for (int o = 16; o; o >>= 1) ss += __shfl_xor_sync(0xffffffffu, ss, o);
    float inv = 1.f / fmaxf(sqrtf(ss), EPS);
    float nn = 0.f;
#pragma unroll
    for (int i = 0; i < 16; i++) {
        float x = v[i] * inv;
        int idx = lane + 32 * i;
        dst[idx] = x;
        eh[idx] = __float2bfloat16(x);
        nn += x * x;
    }
#pragma unroll
    for (int o = 16; o; o >>= 1) nn += __shfl_xor_sync(0xffffffffu, nn, o);
    if (lane == 0) *selfdot = nn;
}

// ---------------- label argmax per support ----------------
__global__ void k_labcls(const float* __restrict__ labels) {
    int n = blockIdx.x * blockDim.x + threadIdx.x;
    if (n >= NS) return;
    const float* r = labels + n * NC;
    float m = r[0]; int mi = 0;
#pragma unroll
    for (int c = 1; c < NC; c++) { float x = r[c]; if (x > m) { m = x; mi = c; } }
    g_labcls[n] = mi;
}

// ---------------- label column sums ----------------
__global__ void k_colsum(const float* __restrict__ labels) {
    __shared__ float sh[256];
    int c = blockIdx.x, tid = threadIdx.x;
    float s = 0.f;
    for (int n = tid; n < NS; n += 256) s += labels[n * NC + c];
    sh[tid] = s;
    __syncthreads();
    for (int st = 128; st; st >>= 1) {
        if (tid < st) sh[tid] += sh[tid + st];
        __syncthreads();
    }
    if (tid == 0) g_cnt[c] = sh[0];
}

// ---------------- centroid partials (atomic-free) ----------------
__global__ void k_cent_part(const float* __restrict__ sup) {
    __shared__ float sp[NC * ND];
    int tid = threadIdx.x;
    for (int i = tid; i < NC * ND; i += 512) sp[i] = 0.f;
    __syncthreads();
    int n0 = blockIdx.x * 32;
    for (int n = 0; n < 32; n++) {
        int c = g_labcls[n0 + n];
        sp[c * ND + tid] += sup[(size_t)(n0 + n) * ND + tid];
    }
    __syncthreads();
    float* dst = g_part + (size_t)blockIdx.x * NC * ND;
    for (int i = tid; i < NC * ND; i += 512) dst[i] = sp[i];
}

__global__ void k_cent_reduce() {
    int i = blockIdx.x * blockDim.x + threadIdx.x;
    if (i >= NC * ND) return;
    float s = 0.f;
    for (int b = 0; b < NPART; b++) s += g_part[(size_t)b * NC * ND + i];
    int c = i / ND;
    g_cent[i] = s / (g_cnt[c] + EPS);
}

__global__ void k_cent_norm() {
    int w = threadIdx.x >> 5, lane = threadIdx.x & 31;
    if (w >= NC) return;
    float v[16];
    float ss = 0.f;
#pragma unroll
    for (int i = 0; i < 16; i++) {
        float x = g_cent[w * ND + lane + 32 * i];
        v[i] = x; ss += x * x;
    }
#pragma unroll
    for (int o = 16; o; o >>= 1) ss += __shfl_xor_sync(0xffffffffu, ss, o);
    float inv = 1.f / fmaxf(sqrtf(ss), EPS);
#pragma unroll
    for (int i = 0; i < 16; i++) g_centn[w * ND + lane + 32 * i] = v[i] * inv;
}

// ---------------- temp_labels: argmax class + softmax per support ----------------
__global__ void k_templabels() {
    __shared__ float sc[NC * ND];
    int tid = threadIdx.x;
    for (int i = tid; i < NC * ND; i += 256) sc[i] = g_centn[i];
    __syncthreads();
    int w = tid >> 5, lane = tid & 31;
    int row = blockIdx.x * 8 + w;
    float acc[NC];
#pragma unroll
    for (int c = 0; c < NC; c++) acc[c] = 0.f;
    const float* sr = g_sn + (size_t)row * ND;
#pragma unroll 4
    for (int i = 0; i < 16; i++) {
        float x = sr[lane + 32 * i];
#pragma unroll
        for (int c = 0; c < NC; c++) acc[c] += x * sc[c * ND + lane + 32 * i];
    }
#pragma unroll
    for (int c = 0; c < NC; c++) {
#pragma unroll
        for (int o = 16; o; o >>= 1) acc[c] += __shfl_xor_sync(0xffffffffu, acc[c], o);
    }
    if (lane == 0) {
        float t[NC];
        float m = -1e30f; int mi = 0;
#pragma unroll
        for (int c = 0; c < NC; c++) {
            t[c] = TAU * acc[c];
            if (t[c] > m) { m = t[c]; mi = c; }
        }
        float s = 0.f;
#pragma unroll
        for (int c = 0; c < NC; c++) { t[c] = expf(t[c] - m); s += t[c]; }
#pragma unroll
        for (int c = 0; c < NC; c++) g_soft[row * NC + c] = t[c] / s;
        g_predcls[row] = mi;
    }
}

// ---------- HMMA GEMM 128x256 tile, 512 threads, 32x64 warp tiles ----------
__device__ __forceinline__ void g_load_stage(uint32_t sb, int buf, int k0,
                                             int brow, int bcol, int tid) {
    uint32_t abase = sb + buf * GSTAGE;
    uint32_t bbase = abase + ASTAGE;
#pragma unroll
    for (int i = 0; i < 2; i++) {
        int u = tid + 512 * i;
        int r = u >> 3, sg = u & 7;
        cp16(abase + swz(r * 128 + sg * 16),
             g_Ah + (size_t)(brow + r) * ND + k0 + sg * 8);
    }
#pragma unroll
    for (int i = 0; i < 4; i++) {
        int u = tid + 512 * i;
        int r = u >> 3, sg = u & 7;
        cp16(bbase + swz(r * 128 + sg * 16),
             g_Bh + (size_t)(bcol + r) * ND + k0 + sg * 8);
    }
}

__global__ __launch_bounds__(512, 1) void k_gemm_mma() {
    extern __shared__ __align__(1024) char smem[];
    uint32_t sb = smem_u32(smem);
    const int tid = threadIdx.x;
    const int brow = blockIdx.y * 128;
    const int bcol = blockIdx.x * 256;
    const int w = tid >> 5, lane = tid & 31;
    const int wm = (w >> 2) * 32;   // 4 warps in m (32 rows each)
    const int wn = (w & 3) * 64;    // 4 warps in n (64 cols each)

    float acc[2][8][4];
#pragma unroll
    for (int a = 0; a < 2; a++)
#pragma unroll
        for (int b = 0; b < 8; b++)
#pragma unroll
            for (int c = 0; c < 4; c++) acc[a][b][c] = 0.f;

    g_load_stage(sb, 0, 0, brow, bcol, tid);
    CP_COMMIT();
    g_load_stage(sb, 1, 64, brow, bcol, tid);
    CP_COMMIT();

    // A frag: row = wm + mt*16 + (lane&15), col byte = cb + ((lane>>4)<<4)
    const u32 a_row = wm + (lane & 15);
    const u32 a_cbo = (lane >> 4) << 4;
    // B frag (paired n8 tiles): row = wn + ntp*16 + (lane&7) + ((lane>>4)<<3)
    const u32 b_row = wn + (lane & 7) + ((lane >> 4) << 3);
    const u32 b_cbo = ((lane >> 3) & 1) << 4;

#pragma unroll 1
    for (int it = 0; it < GITERS; it++) {
        asm volatile("cp.async.wait_group 1;" ::: "memory");
        __syncthreads();

        uint32_t As = sb + (it & 1) * GSTAGE;
        uint32_t Bs = As + ASTAGE;
#pragma unroll
        for (int ks = 0; ks < 4; ks++) {
            u32 cb = ks * 32;
            uint32_t af[2][4], bf[4][4];
#pragma unroll
            for (int mt = 0; mt < 2; mt++)
                ldsm4(af[mt], As + swz((a_row + mt * 16) * 128 + cb + a_cbo));
#pragma unroll
            for (int ntp = 0; ntp < 4; ntp++)
                ldsm4(bf[ntp], Bs + swz((b_row + ntp * 16) * 128 + cb + b_cbo));
#pragma unroll
            for (int mt = 0; mt < 2; mt++)
#pragma unroll
                for (int nt = 0; nt < 8; nt++)
                    mma16816(acc[mt][nt], af[mt], &bf[nt >> 1][(nt & 1) * 2]);
        }
        __syncthreads();
        if (it + 2 < GITERS)
            g_load_stage(sb, it & 1, (it + 2) * 64, brow, bcol, tid);
        CP_COMMIT();
    }

    // ---- register-resident epilogue: per-row top-4 within this 64-col warp tile ----
    const int g = lane >> 2;        // row group 0..7
    const int qt = lane & 3;        // quad thread
    const int tile64 = blockIdx.x * 4 + (w & 3);
    const u32 colbase = (u32)(bcol + wn + qt * 2);
#pragma unroll
    for (int mt = 0; mt < 2; mt++) {
#pragma unroll
        for (int h = 0; h < 2; h++) {
            int row = brow + wm + mt * 16 + h * 8 + g;
            u64 s0 = 0, s1 = 0, s2 = 0, s3 = 0;
#pragma unroll
            for (int nt = 0; nt < 8; nt++) {
#pragma unroll
                for (int e = 0; e < 2; e++) {
                    u64 p = fpack(acc[mt][nt][h * 2 + e], colbase + nt * 8 + e);
                    if (p > s3) {
                        s3 = p;
                        CE(s2, s3); CE(s1, s2); CE(s0, s1);
                    }
                }
            }
            // merge sorted-4 lists across the quad (xor 1, then xor 2)
#pragma unroll
            for (int d = 1; d <= 2; d <<= 1) {
                u64 t0 = __shfl_xor_sync(0xffffffffu, s0, d);
                u64 t1 = __shfl_xor_sync(0xffffffffu, s1, d);
                u64 t2 = __shfl_xor_sync(0xffffffffu, s2, d);
                u64 t3 = __shfl_xor_sync(0xffffffffu, s3, d);
                s0 = s0 > t3 ? s0 : t3;
                s1 = s1 > t2 ? s1 : t2;
                s2 = s2 > t1 ? s2 : t1;
                s3 = s3 > t0 ? s3 : t0;
                CE(s0, s2); CE(s1, s3); CE(s0, s1); CE(s2, s3);
            }
            if (qt == 0) {
                u64* dst = g_cand + ((size_t)row * NT64 + tile64) * 4;
                dst[0] = s0; dst[1] = s1; dst[2] = s2; dst[3] = s3;
            }
        }
    }
}

// ------- per-row: merge 1024 candidates -> top-16 -> exact rescore -> top-8 ------
__global__ void k_select(float* __restrict__ out) {
    __shared__ float zrow[ND];
    __shared__ u64 sh_w[8];
    __shared__ u64 sh_win;
    __shared__ u64 wlist[KCAND];
    __shared__ int widx[KCAND];
    __shared__ float cdist[KCAND];
    __shared__ int sel[KTOP];
    __shared__ float st[NC], so[NC], ssum[2];
    const int row = blockIdx.x;
    const int tid = threadIdx.x;
    const int w = tid >> 5, lane = tid & 31;

    zrow[tid] = g_zn[(size_t)row * ND + tid];
    zrow[tid + 256] = g_zn[(size_t)row * ND + tid + 256];

    const u64* cand = g_cand + (size_t)row * (NT64 * 4);
    u64 l0 = cand[tid], l1 = cand[tid + 256], l2 = cand[tid + 512], l3 = cand[tid + 768];
    CE(l0, l1); CE(l2, l3); CE(l0, l2); CE(l1, l3); CE(l1, l2);

#pragma unroll 1
    for (int r = 0; r < KCAND; r++) {
        u64 m = l0;
#pragma unroll
        for (int o = 16; o; o >>= 1) {
            u64 p = __shfl_xor_sync(0xffffffffu, m, o);
            if (p > m) m = p;
        }
        if (lane == 0) sh_w[w] = m;
        __syncthreads();
        if (tid == 0) {
            u64 b = sh_w[0];
#pragma unroll
            for (int j = 1; j < 8; j++) if (sh_w[j] > b) b = sh_w[j];
            sh_win = b;
            wlist[r] = b;
        }
        __syncthreads();
        u64 win = sh_win;
        if (l0 == win) { l0 = l1; l1 = l2; l2 = l3; l3 = 0; }
        __syncthreads();
    }

    if (tid < KCAND) widx[tid] = (int)FIDX(wlist[tid]);
    __syncthreads();

    // exact fp32 rescore: dist = XX + YY - 2*dot
    {
        float XXr = g_XX[row];
        for (int candi = w; candi < KCAND; candi += 8) {
            int n = widx[candi];
            const float* sr = g_sn + (size_t)n * ND;
            float d = 0.f;
#pragma unroll 4
            for (int i = 0; i < 16; i++) d += zrow[lane + 32 * i] * sr[lane + 32 * i];
#pragma unroll
            for (int o = 16; o; o >>= 1) d += __shfl_xor_sync(0xffffffffu, d, o);
            if (lane == 0) cdist[candi] = XXr + g_YY[n] - 2.f * d;
        }
    }
    __syncthreads();

    // select 8 smallest dist (tie -> lower support index)
    if (tid == 0) {
        unsigned used = 0;
#pragma unroll
        for (int k = 0; k < KTOP; k++) {
            float bd = 1e30f; int bi = -1, bn = 1 << 30;
#pragma unroll
            for (int c = 0; c < KCAND; c++) {
                if (used & (1u << c)) continue;
                float dc = cdist[c]; int nc_ = widx[c];
                if (dc < bd || (dc == bd && nc_ < bn)) { bd = dc; bi = c; bn = nc_; }
            }
            used |= 1u << bi;
            sel[k] = bn;
        }
    }
    __syncthreads();

    if (tid < NC) {
        float o = 0.f, tg = 0.f;
#pragma unroll
        for (int k = 0; k < KTOP; k++) {
            int n = sel[k];
            o += g_soft[n * NC + tid];
            tg += (g_predcls[n] == tid) ? 1.f : 0.f;
        }
        st[tid] = tg; so[tid] = o;
    }
    __syncthreads();
    if (tid == 0) {
        float ts = 0.f, os = 0.f;
#pragma unroll
        for (int c = 0; c < NC; c++) { ts += st[c]; os += so[c]; }
        ssum[0] = ts; ssum[1] = os;
    }
    __syncthreads();
    if (tid < NC) {
        out[(size_t)NB * NC + row * NC + tid] = st[tid] / (ssum[0] + EPS);
        out[(size_t)2 * NB * NC + row * NC + tid] = so[tid] / (ssum[1] + EPS);
    }
}

// ---------------- logits = TAU * zn @ centn^T ----------------
__global__ void k_logits(float* __restrict__ out) {
    __shared__ float sc[NC * ND];
    int tid = threadIdx.x;
    for (int i = tid; i < NC * ND; i += 256) sc[i] = g_centn[i];
    __syncthreads();
    int w = tid >> 5, lane = tid & 31;
    int row = blockIdx.x * 8 + w;
    float acc[NC];
#pragma unroll
    for (int c = 0; c < NC; c++) acc[c] = 0.f;
    const float* zr = g_zn + (size_t)row * ND;
#pragma unroll 4
    for (int i = 0; i < 16; i++) {
        float x = zr[lane + 32 * i];
#pragma unroll
        for (int c = 0; c < NC; c++) acc[c] += x * sc[c * ND + lane + 32 * i];
    }
#pragma unroll
    for (int c = 0; c < NC; c++) {
#pragma unroll
        for (int o = 16; o; o >>= 1) acc[c] += __shfl_xor_sync(0xffffffffu, acc[c], o);
    }
    if (lane == 0) {
#pragma unroll
        for (int c = 0; c < NC; c++) out[row * NC + c] = TAU * acc[c];
    }
}

// ---------------- launch ----------------
extern "C" void kernel_launch(void* const* d_in, const int* in_sizes, int n_in,
                              void* d_out, int out_size) {
    const float* z = (const float*)d_in[0];
    const float* supports = (const float*)d_in[1];
    const float* labels = (const float*)d_in[2];
    float* out = (float*)d_out;

    cudaFuncSetAttribute(k_gemm_mma, cudaFuncAttributeMaxDynamicSharedMemorySize,
                         GEMM_SMEM);

    // k_gemm_mma stays in the ncu-profiled launch slot (#4).
    k_normalize<<<(NB + NS) / 8, 256>>>(z, supports);
    k_labcls<<<NS / 256, 256>>>(labels);
    k_colsum<<<NC, 256>>>(labels);
    dim3 gg(NS / 256, NB / 128);
    k_gemm_mma<<<gg, 512, GEMM_SMEM>>>();
    k_cent_part<<<NPART, 512>>>(supports);
    k_cent_reduce<<<(NC * ND + 255) / 256, 256>>>();
    k_cent_norm<<<1, NC * 32>>>();
    k_templabels<<<NS / 8, 256>>>();
    k_select<<<NB, 256>>>(out);
    k_logits<<<NB / 8, 256>>>(out);
}

// round 8
// speedup vs baseline: 3.4620x; 1.0061x over previous
#include <cuda_runtime.h>
#include <cuda_bf16.h>
#include <math.h>
#include <stdint.h>

typedef unsigned long long u64;
typedef unsigned int u32;

// Problem constants
#define NB 2048     // queries
#define NS 16384    // supports
#define ND 512      // dim
#define NC 17       // classes
#define KTOP 8
#define KCAND 16    // candidates rescored exactly
#define TAU 10.0f
#define EPS 1e-12f

#define GITERS 8          // ND / 64
#define ASTAGE 16384      // 128 rows x 128B
#define BSTAGE 32768      // 256 rows x 128B
#define GSTAGE (ASTAGE + BSTAGE)
#define GEMM_SMEM (3 * GSTAGE)   // 144 KB, 3-stage pipeline
#define NT64 256          // NS / 64 column tiles per row
#define NPART 512         // centroid partial chunks

// ---------------- scratch (device globals; no runtime alloc) ----------------
__device__ float g_zn[NB * ND];            // normalized z (fp32, exact)
__device__ float g_sn[NS * ND];            // normalized supports (fp32, exact)
__device__ float g_XX[NB];                 // sum(zn^2) per row
__device__ float g_YY[NS];                 // sum(sn^2) per support
__device__ float g_cent[NC * ND];
__device__ float g_centn[NC * ND];
__device__ float g_cnt[NC];
__device__ int   g_labcls[NS];
__device__ int   g_predcls[NS];
__device__ float g_soft[NS * NC];
__device__ float g_part[NPART * NC * ND];
__device__ __align__(16) __nv_bfloat16 g_Ah[NB * ND];   // bf16(zn)
__device__ __align__(16) __nv_bfloat16 g_Bh[NS * ND];   // bf16(sn)
__device__ u64 g_cand[(size_t)NB * NT64 * 4];           // per-64col-tile top-4 (16 MB)

// ---------------- PTX helpers ----------------
__device__ __forceinline__ uint32_t smem_u32(const void* p) {
    uint32_t a;
    asm("{ .reg .u64 t; cvta.to.shared.u64 t, %1; cvt.u32.u64 %0, t; }" : "=r"(a) : "l"(p));
    return a;
}
__device__ __forceinline__ void cp16(uint32_t saddr, const void* g) {
    asm volatile("cp.async.cg.shared.global [%0], [%1], 16;" :: "r"(saddr), "l"(g));
}
#define CP_COMMIT() asm volatile("cp.async.commit_group;" ::: "memory")

__device__ __forceinline__ void ldsm4(uint32_t* r, uint32_t addr) {
    asm volatile("ldmatrix.sync.aligned.m8n8.x4.shared.b16 {%0,%1,%2,%3}, [%4];"
        : "=r"(r[0]), "=r"(r[1]), "=r"(r[2]), "=r"(r[3]) : "r"(addr));
}
__device__ __forceinline__ void mma16816(float* d, const uint32_t* a, const uint32_t* b) {
    asm volatile(
        "mma.sync.aligned.m16n8k16.row.col.f32.bf16.bf16.f32 "
        "{%0,%1,%2,%3}, {%4,%5,%6,%7}, {%8,%9}, {%0,%1,%2,%3};"
        : "+f"(d[0]), "+f"(d[1]), "+f"(d[2]), "+f"(d[3])
        : "r"(a[0]), "r"(a[1]), "r"(a[2]), "r"(a[3]), "r"(b[0]), "r"(b[1]));
}
__device__ __forceinline__ uint32_t swz(uint32_t o) { return o ^ ((o >> 3) & 0x70); }

// monotone float encoding: enc(a) > enc(b) <=> a > b
__device__ __forceinline__ u32 fenc(float x) {
    u32 b = __float_as_uint(x);
    return (b & 0x80000000u) ? ~b : (b | 0x80000000u);
}
__device__ __forceinline__ u64 fpack(float x, u32 col) {
    return ((u64)fenc(x) << 32) | (u64)(0xFFFFFFFFu - col);
}
#define FIDX(p) (0xFFFFFFFFu - (u32)(p))

#define CE(a, b) do { if ((a) < (b)) { u64 _t = (a); (a) = (b); (b) = _t; } } while (0)

// ---------------- normalization + bf16 hi + self-dot ----------------
__global__ void k_normalize(const float* __restrict__ z, const float* __restrict__ sup) {
    int gw = (blockIdx.x * blockDim.x + threadIdx.x) >> 5;
    int lane = threadIdx.x & 31;
    if (gw >= NB + NS) return;
    const float* src;
    float* dst;
    __nv_bfloat16* eh;
    float* selfdot;
    bool isA = gw < NB;
    int r = isA ? gw : gw - NB;
    if (isA) { src = z + (size_t)r * ND; dst = g_zn + (size_t)r * ND; eh = g_Ah + (size_t)r * ND; selfdot = g_XX + r; }
    else     { src = sup + (size_t)r * ND; dst = g_sn + (size_t)r * ND; eh = g_Bh + (size_t)r * ND; selfdot = g_YY + r; }
    float v[16];
    float ss = 0.f;
#pragma unroll
    for (int i = 0; i < 16; i++) {
        float x = src[lane + 32 * i];
        v[i] = x;
        ss += x * x;
    }
#pragma unroll
    for (int o = 16; o; o >>= 1) ss += __shfl_xor_sync(0xffffffffu, ss, o);
    float inv = 1.f / fmaxf(sqrtf(ss), EPS);
    float nn = 0.f;
#pragma unroll
    for (int i = 0; i < 16; i++) {
        float x = v[i] * inv;
        int idx = lane + 32 * i;
        dst[idx] = x;
        eh[idx] = __float2bfloat16(x);
        nn += x * x;
    }
#pragma unroll
    for (int o = 16; o; o >>= 1) nn += __shfl_xor_sync(0xffffffffu, nn, o);
    if (lane == 0) *selfdot = nn;
}

// ---------------- label argmax per support ----------------
__global__ void k_labcls(const float* __restrict__ labels) {
    int n = blockIdx.x * blockDim.x + threadIdx.x;
    if (n >= NS) return;
    const float* r = labels + n * NC;
    float m = r[0]; int mi = 0;
#pragma unroll
    for (int c = 1; c < NC; c++) { float x = r[c]; if (x > m) { m = x; mi = c; } }
    g_labcls[n] = mi;
}

// ---------------- label column sums ----------------
__global__ void k_colsum(const float* __restrict__ labels) {
    __shared__ float sh[256];
    int c = blockIdx.x, tid = threadIdx.x;
    float s = 0.f;
    for (int n = tid; n < NS; n += 256) s += labels[n * NC + c];
    sh[tid] = s;
    __syncthreads();
    for (int st = 128; st; st >>= 1) {
        if (tid < st) sh[tid] += sh[tid + st];
        __syncthreads();
    }
    if (tid == 0) g_cnt[c] = sh[0];
}

// ---------------- centroid partials (atomic-free) ----------------
__global__ void k_cent_part(const float* __restrict__ sup) {
    __shared__ float sp[NC * ND];
    int tid = threadIdx.x;
    for (int i = tid; i < NC * ND; i += 512) sp[i] = 0.f;
    __syncthreads();
    int n0 = blockIdx.x * 32;
    for (int n = 0; n < 32; n++) {
        int c = g_labcls[n0 + n];
        sp[c * ND + tid] += sup[(size_t)(n0 + n) * ND + tid];
    }
    __syncthreads();
    float* dst = g_part + (size_t)blockIdx.x * NC * ND;
    for (int i = tid; i < NC * ND; i += 512) dst[i] = sp[i];
}

__global__ void k_cent_reduce() {
    int i = blockIdx.x * blockDim.x + threadIdx.x;
    if (i >= NC * ND) return;
    float s = 0.f;
    for (int b = 0; b < NPART; b++) s += g_part[(size_t)b * NC * ND + i];
    int c = i / ND;
    g_cent[i] = s / (g_cnt[c] + EPS);
}

__global__ void k_cent_norm() {
    int w = threadIdx.x >> 5, lane = threadIdx.x & 31;
    if (w >= NC) return;
    float v[16];
    float ss = 0.f;
#pragma unroll
    for (int i = 0; i < 16; i++) {
        float x = g_cent[w * ND + lane + 32 * i];
        v[i] = x; ss += x * x;
    }
#pragma unroll
    for (int o = 16; o; o >>= 1) ss += __shfl_xor_sync(0xffffffffu, ss, o);
    float inv = 1.f / fmaxf(sqrtf(ss), EPS);
#pragma unroll
    for (int i = 0; i < 16; i++) g_centn[w * ND + lane + 32 * i] = v[i] * inv;
}

// ---------------- temp_labels: argmax class + softmax per support ----------------
__global__ void k_templabels() {
    __shared__ float sc[NC * ND];
    int tid = threadIdx.x;
    for (int i = tid; i < NC * ND; i += 256) sc[i] = g_centn[i];
    __syncthreads();
    int w = tid >> 5, lane = tid & 31;
    int row = blockIdx.x * 8 + w;
    float acc[NC];
#pragma unroll
    for (int c = 0; c < NC; c++) acc[c] = 0.f;
    const float* sr = g_sn + (size_t)row * ND;
#pragma unroll 4
    for (int i = 0; i < 16; i++) {
        float x = sr[lane + 32 * i];
#pragma unroll
        for (int c = 0; c < NC; c++) acc[c] += x * sc[c * ND + lane + 32 * i];
    }
#pragma unroll
    for (int c = 0; c < NC; c++) {
#pragma unroll
        for (int o = 16; o; o >>= 1) acc[c] += __shfl_xor_sync(0xffffffffu, acc[c], o);
    }
    if (lane == 0) {
        float t[NC];
        float m = -1e30f; int mi = 0;
#pragma unroll
        for (int c = 0; c < NC; c++) {
            t[c] = TAU * acc[c];
            if (t[c] > m) { m = t[c]; mi = c; }
        }
        float s = 0.f;
#pragma unroll
        for (int c = 0; c < NC; c++) { t[c] = expf(t[c] - m); s += t[c]; }
#pragma unroll
        for (int c = 0; c < NC; c++) g_soft[row * NC + c] = t[c] / s;
        g_predcls[row] = mi;
    }
}

// ---------- HMMA GEMM 128x256 tile, 512 threads, strength-reduced addressing ----------
__global__ __launch_bounds__(512, 1) void k_gemm_mma() {
    extern __shared__ __align__(1024) char smem[];
    uint32_t sb = smem_u32(smem);
    const int tid = threadIdx.x;
    const int brow = blockIdx.y * 128;
    const int bcol = blockIdx.x * 256;
    const int w = tid >> 5, lane = tid & 31;
    const int wm = (w >> 2) * 32;   // 4 warps in m (32 rows each)
    const int wn = (w & 3) * 64;    // 4 warps in n (64 cols each)

    // ---- loader precompute (all per-thread constants; stage/k0 are immediates/adds) ----
    const int lr = tid >> 3, lsg = tid & 7;
    const u32 ldoff = (u32)(lr * 128 + ((lsg * 16) ^ ((lr & 7) << 4)));
    const u32 adst = sb + ldoff;
    const u32 bdst = sb + ASTAGE + ldoff;
    const __nv_bfloat16* asrc = g_Ah + (size_t)(brow + lr) * ND + lsg * 8;
    const __nv_bfloat16* bsrc = g_Bh + (size_t)(bcol + lr) * ND + lsg * 8;

    auto load_stage = [&](u32 soff, int k0) {
        cp16(adst + soff, asrc + k0);
        cp16(adst + soff + 8192, asrc + k0 + (size_t)64 * ND);
#pragma unroll
        for (int i = 0; i < 4; i++)
            cp16(bdst + soff + i * 8192, bsrc + k0 + (size_t)i * 64 * ND);
        CP_COMMIT();
    };

    // ---- fragment address precompute ----
    // swz(r*128 + X) = r*128 + (X ^ ((r&7)<<4)); r&7 == lane&7 for all our rows.
    const u32 m16 = ((u32)lane & 1) << 4;              // mask bit 4
    const u32 m60 = (((u32)lane >> 1) & 3) << 5;       // mask bits 5-6
    const u32 ra = (u32)((wm + (lane & 15)) * 128) + ((((u32)lane >> 4) << 4) ^ m16);
    const u32 rb = (u32)(ASTAGE + (wn + (lane & 7) + ((lane >> 4) << 3)) * 128)
                 + (((((u32)lane >> 3) & 1) << 4) ^ m16);

    float acc[2][8][4];
#pragma unroll
    for (int a = 0; a < 2; a++)
#pragma unroll
        for (int b = 0; b < 8; b++)
#pragma unroll
            for (int c = 0; c < 4; c++) acc[a][b][c] = 0.f;

    load_stage(0, 0);
    load_stage(GSTAGE, 64);

    u32 cs_off = 0;            // compute-stage smem offset
    u32 ls_off = 2 * GSTAGE;   // load-stage smem offset
#pragma unroll 1
    for (int it = 0; it < GITERS; it++) {
        if (it < GITERS - 1) asm volatile("cp.async.wait_group 1;" ::: "memory");
        else                 asm volatile("cp.async.wait_group 0;" ::: "memory");
        __syncthreads();

        if (it + 2 < GITERS) {
            load_stage(ls_off, (it + 2) * 64);
            ls_off = (ls_off == 2 * GSTAGE) ? 0 : ls_off + GSTAGE;
        }

        const u32 Ast = sb + cs_off + ra;
        const u32 Bst = sb + cs_off + rb;
#pragma unroll
        for (int ks = 0; ks < 4; ks++) {
            const u32 q = ((u32)(ks * 32)) ^ m60;
            uint32_t af[2][4], bf[4][4];
            u32 aq = Ast + q, bq = Bst + q;
            ldsm4(af[0], aq);
            ldsm4(af[1], aq + 2048);
#pragma unroll
            for (int ntp = 0; ntp < 4; ntp++)
                ldsm4(bf[ntp], bq + ntp * 2048);
#pragma unroll
            for (int mt = 0; mt < 2; mt++)
#pragma unroll
                for (int nt = 0; nt < 8; nt++)
                    mma16816(acc[mt][nt], af[mt], &bf[nt >> 1][(nt & 1) * 2]);
        }
        cs_off = (cs_off == 2 * GSTAGE) ? 0 : cs_off + GSTAGE;
    }

    // ---- register-resident epilogue: per-row top-4 within this 64-col warp tile ----
    const int g = lane >> 2;        // row group 0..7
    const int qt = lane & 3;        // quad thread
    const int tile64 = blockIdx.x * 4 + (w & 3);
    const u32 colbase = (u32)(bcol + wn + qt * 2);
#pragma unroll
    for (int mt = 0; mt < 2; mt++) {
#pragma unroll
        for (int h = 0; h < 2; h++) {
            int row = brow + wm + mt * 16 + h * 8 + g;
            u64 s0 = 0, s1 = 0, s2 = 0, s3 = 0;
#pragma unroll
            for (int nt = 0; nt < 8; nt++) {
#pragma unroll
                for (int e = 0; e < 2; e++) {
                    u64 p = fpack(acc[mt][nt][h * 2 + e], colbase + nt * 8 + e);
                    if (p > s3) {
                        s3 = p;
                        CE(s2, s3); CE(s1, s2); CE(s0, s1);
                    }
                }
            }
            // merge sorted-4 lists across the quad (xor 1, then xor 2)
#pragma unroll
            for (int d = 1; d <= 2; d <<= 1) {
                u64 t0 = __shfl_xor_sync(0xffffffffu, s0, d);
                u64 t1 = __shfl_xor_sync(0xffffffffu, s1, d);
                u64 t2 = __shfl_xor_sync(0xffffffffu, s2, d);
                u64 t3 = __shfl_xor_sync(0xffffffffu, s3, d);
                s0 = s0 > t3 ? s0 : t3;
                s1 = s1 > t2 ? s1 : t2;
                s2 = s2 > t1 ? s2 : t1;
                s3 = s3 > t0 ? s3 : t0;
                CE(s0, s2); CE(s1, s3); CE(s0, s1); CE(s2, s3);
            }
            if (qt == 0) {
                u64* dst = g_cand + ((size_t)row * NT64 + tile64) * 4;
                dst[0] = s0; dst[1] = s1; dst[2] = s2; dst[3] = s3;
            }
        }
    }
}

// ------- per-row: merge 1024 candidates -> top-16 -> exact rescore -> top-8 ------
__global__ void k_select(float* __restrict__ out) {
    __shared__ float zrow[ND];
    __shared__ u64 sh_w[8];
    __shared__ u64 sh_win;
    __shared__ u64 wlist[KCAND];
    __shared__ int widx[KCAND];
    __shared__ float cdist[KCAND];
    __shared__ int sel[KTOP];
    __shared__ float st[NC], so[NC], ssum[2];
    const int row = blockIdx.x;
    const int tid = threadIdx.x;
    const int w = tid >> 5, lane = tid & 31;

    zrow[tid] = g_zn[(size_t)row * ND + tid];
    zrow[tid + 256] = g_zn[(size_t)row * ND + tid + 256];

    const u64* cand = g_cand + (size_t)row * (NT64 * 4);
    u64 l0 = cand[tid], l1 = cand[tid + 256], l2 = cand[tid + 512], l3 = cand[tid + 768];
    CE(l0, l1); CE(l2, l3); CE(l0, l2); CE(l1, l3); CE(l1, l2);

#pragma unroll 1
    for (int r = 0; r < KCAND; r++) {
        u64 m = l0;
#pragma unroll
        for (int o = 16; o; o >>= 1) {
            u64 p = __shfl_xor_sync(0xffffffffu, m, o);
            if (p > m) m = p;
        }
        if (lane == 0) sh_w[w] = m;
        __syncthreads();
        if (tid == 0) {
            u64 b = sh_w[0];
#pragma unroll
            for (int j = 1; j < 8; j++) if (sh_w[j] > b) b = sh_w[j];
            sh_win = b;
            wlist[r] = b;
        }
        __syncthreads();
        u64 win = sh_win;
        if (l0 == win) { l0 = l1; l1 = l2; l2 = l3; l3 = 0; }
        __syncthreads();
    }

    if (tid < KCAND) widx[tid] = (int)FIDX(wlist[tid]);
    __syncthreads();

    // exact fp32 rescore: dist = XX + YY - 2*dot
    {
        float XXr = g_XX[row];
        for (int candi = w; candi < KCAND; candi += 8) {
            int n = widx[candi];
            const float* sr = g_sn + (size_t)n * ND;
            float d = 0.f;
#pragma unroll 4
            for (int i = 0; i < 16; i++) d += zrow[lane + 32 * i] * sr[lane + 32 * i];
#pragma unroll
            for (int o = 16; o; o >>= 1) d += __shfl_xor_sync(0xffffffffu, d, o);
            if (lane == 0) cdist[candi] = XXr + g_YY[n] - 2.f * d;
        }
    }
    __syncthreads();

    // select 8 smallest dist (tie -> lower support index)
    if (tid == 0) {
        unsigned used = 0;
#pragma unroll
        for (int k = 0; k < KTOP; k++) {
            float bd = 1e30f; int bi = -1, bn = 1 << 30;
#pragma unroll
            for (int c = 0; c < KCAND; c++) {
                if (used & (1u << c)) continue;
                float dc = cdist[c]; int nc_ = widx[c];
                if (dc < bd || (dc == bd && nc_ < bn)) { bd = dc; bi = c; bn = nc_; }
            }
            used |= 1u << bi;
            sel[k] = bn;
        }
    }
    __syncthreads();

    if (tid < NC) {
        float o = 0.f, tg = 0.f;
#pragma unroll
        for (int k = 0; k < KTOP; k++) {
            int n = sel[k];
            o += g_soft[n * NC + tid];
            tg += (g_predcls[n] == tid) ? 1.f : 0.f;
        }
        st[tid] = tg; so[tid] = o;
    }
    __syncthreads();
    if (tid == 0) {
        float ts = 0.f, os = 0.f;
#pragma unroll
        for (int c = 0; c < NC; c++) { ts += st[c]; os += so[c]; }
        ssum[0] = ts; ssum[1] = os;
    }
    __syncthreads();
    if (tid < NC) {
        out[(size_t)NB * NC + row * NC + tid] = st[tid] / (ssum[0] + EPS);
        out[(size_t)2 * NB * NC + row * NC + tid] = so[tid] / (ssum[1] + EPS);
    }
}

// ---------------- logits = TAU * zn @ centn^T ----------------
__global__ void k_logits(float* __restrict__ out) {
    __shared__ float sc[NC * ND];
    int tid = threadIdx.x;
    for (int i = tid; i < NC * ND; i += 256) sc[i] = g_centn[i];
    __syncthreads();
    int w = tid >> 5, lane = tid & 31;
    int row = blockIdx.x * 8 + w;
    float acc[NC];
#pragma unroll
    for (int c = 0; c < NC; c++) acc[c] = 0.f;
    const float* zr = g_zn + (size_t)row * ND;
#pragma unroll 4
    for (int i = 0; i < 16; i++) {
        float x = zr[lane + 32 * i];
#pragma unroll
        for (int c = 0; c < NC; c++) acc[c] += x * sc[c * ND + lane + 32 * i];
    }
#pragma unroll
    for (int c = 0; c < NC; c++) {
#pragma unroll
        for (int o = 16; o; o >>= 1) acc[c] += __shfl_xor_sync(0xffffffffu, acc[c], o);
    }
    if (lane == 0) {
#pragma unroll
        for (int c = 0; c < NC; c++) out[row * NC + c] = TAU * acc[c];
    }
}

// ---------------- launch ----------------
extern "C" void kernel_launch(void* const* d_in, const int* in_sizes, int n_in,
                              void* d_out, int out_size) {
    const float* z = (const float*)d_in[0];
    const float* supports = (const float*)d_in[1];
    const float* labels = (const float*)d_in[2];
    float* out = (float*)d_out;

    cudaFuncSetAttribute(k_gemm_mma, cudaFuncAttributeMaxDynamicSharedMemorySize,
                         GEMM_SMEM);

    // k_gemm_mma stays in the ncu-profiled launch slot (#4).
    k_normalize<<<(NB + NS) / 8, 256>>>(z, supports);
    k_labcls<<<NS / 256, 256>>>(labels);
    k_colsum<<<NC, 256>>>(labels);
    dim3 gg(NS / 256, NB / 128);
    k_gemm_mma<<<gg, 512, GEMM_SMEM>>>();
    k_cent_part<<<NPART, 512>>>(supports);
    k_cent_reduce<<<(NC * ND + 255) / 256, 256>>>();
    k_cent_norm<<<1, NC * 32>>>();
    k_templabels<<<NS / 8, 256>>>();
    k_select<<<NB, 256>>>(out);
    k_logits<<<NB / 8, 256>>>(out);
}